// round 11
// baseline (speedup 1.0000x reference)
#include <cuda_runtime.h>
#include <cuda_bf16.h>
#include <math.h>
#include <stdint.h>

#define kT   512
#define kB   64
#define kH   1024
#define kBH  65536
#define kTB  32768
#define kTBH 33554432

typedef __nv_bfloat16 bf16;

// ---------------------------------------------------------------------------
// Scratch (device globals; allocations forbidden)
// ---------------------------------------------------------------------------
struct __align__(16) Scratch {
    float X[kTBH];                        // X0 = input @ W_ih0^T + biases
    bf16  Ahi[kTBH], Alo[kTBH];           // split input
    bf16  Whi[4][kH * kH];                // split weights: ih0, hh0, ih1, hh1
    bf16  Wlo[4][kH * kH];
    float bias[2][kH];
    bf16  hinhi[2 * kBH], hinlo[2 * kBH]; // split initial h (layer0, layer1)
};
__device__ Scratch g_s;

// write-once hidden-state histories (bf16 split)
__device__ bf16 g_h0hi[kTBH], g_h0lo[kTBH];
__device__ bf16 g_h1hi[kTBH], g_h1lo[kTBH];

// k-split partials: [slot][mt][kc][64*128]
__device__ float g_p0[2][8][16][64 * 128];
__device__ float g_p1[2][8][16][64 * 128];

// dataflow flags (monotonic counters; fan-in 16)
__device__ int g_pf0[kT][8], g_pf1[kT][8];
__device__ int g_hf0[kT][8], g_hf1[kT][8];

// ---------------------------------------------------------------------------
// Warp MMA primitives (baseline ISA: HMMA + ldmatrix)
// ---------------------------------------------------------------------------
__device__ __forceinline__ uint32_t smem_u32(const void* p) {
    uint32_t r;
    asm("{ .reg .u64 t; cvta.to.shared.u64 t, %1; cvt.u32.u64 %0, t; }" : "=r"(r) : "l"(p));
    return r;
}
#define LDSM4(r, addr)                                                        \
    asm volatile("ldmatrix.sync.aligned.m8n8.x4.shared.b16 {%0,%1,%2,%3}, [%4];" \
        : "=r"((r)[0]), "=r"((r)[1]), "=r"((r)[2]), "=r"((r)[3]) : "r"(addr))
#define HMMA(d, a, b)                                                         \
    asm volatile("mma.sync.aligned.m16n8k16.row.col.f32.bf16.bf16.f32 "       \
        "{%0,%1,%2,%3}, {%4,%5,%6,%7}, {%8,%9}, {%0,%1,%2,%3};"               \
        : "+f"((d)[0]), "+f"((d)[1]), "+f"((d)[2]), "+f"((d)[3])              \
        : "r"((a)[0]), "r"((a)[1]), "r"((a)[2]), "r"((a)[3]),                 \
          "r"((b)[0]), "r"((b)[1]))

__device__ __forceinline__ void spin_ge(const int* f, int n) {
    while (true) {
        int v;
        asm volatile("ld.acquire.gpu.global.s32 %0, [%1];" : "=r"(v) : "l"(f));
        if (v >= n) break;
        __nanosleep(20);
    }
}

// ---------------------------------------------------------------------------
// prep kernels
// ---------------------------------------------------------------------------
__global__ void split_pair(const float* __restrict__ s, bf16* __restrict__ hi,
                           bf16* __restrict__ lo, int n4) {
    int stride = gridDim.x * blockDim.x;
    for (int i = blockIdx.x * blockDim.x + threadIdx.x; i < n4; i += stride) {
        float4 v = ((const float4*)s)[i];
        bf16 h0 = __float2bfloat16(v.x), h1 = __float2bfloat16(v.y);
        bf16 h2 = __float2bfloat16(v.z), h3 = __float2bfloat16(v.w);
        ((__nv_bfloat162*)hi)[i * 2 + 0] = __halves2bfloat162(h0, h1);
        ((__nv_bfloat162*)hi)[i * 2 + 1] = __halves2bfloat162(h2, h3);
        ((__nv_bfloat162*)lo)[i * 2 + 0] = __halves2bfloat162(
            __float2bfloat16(v.x - __bfloat162float(h0)),
            __float2bfloat16(v.y - __bfloat162float(h1)));
        ((__nv_bfloat162*)lo)[i * 2 + 1] = __halves2bfloat162(
            __float2bfloat16(v.z - __bfloat162float(h2)),
            __float2bfloat16(v.w - __bfloat162float(h3)));
    }
}
__global__ void bias2(const float* a, const float* b, const float* c,
                      const float* d, float* o0, float* o1) {
    int i = blockIdx.x * 256 + threadIdx.x;
    if (i < kH) { o0[i] = a[i] + b[i]; o1[i] = c[i] + d[i]; }
}
__global__ void zero_flags() {
    int i = blockIdx.x * 256 + threadIdx.x;
    if (i < kT * 8) {
        ((int*)g_pf0)[i] = 0; ((int*)g_pf1)[i] = 0;
        ((int*)g_hf0)[i] = 0; ((int*)g_hf1)[i] = 0;
    }
}

// ---------------------------------------------------------------------------
// Big HMMA GEMM for X0 (proven R4 kernel, unchanged)
// ---------------------------------------------------------------------------
__global__ void __launch_bounds__(256) gemm_mma(
    const bf16* __restrict__ Ahi, const bf16* __restrict__ Alo,
    const bf16* __restrict__ Whi, const bf16* __restrict__ Wlo,
    const float* __restrict__ bias, float* __restrict__ C)
{
    extern __shared__ char sm[];
    enum { RS = 144, BUF = 128 * 144 };
    char* pAh = sm;            char* pAl = sm + BUF;
    char* pWh = sm + 2 * BUF;  char* pWl = sm + 3 * BUF;

    const int tid = threadIdx.x, lane = tid & 31, wid = tid >> 5;
    const int n0 = blockIdx.x * 128, m0 = blockIdx.y * 128;
    const int wm = (wid >> 1) * 32, wn = (wid & 1) * 64;

    const uint32_t aOffH = smem_u32(pAh) + (wm + (lane & 15)) * RS + (lane >> 4) * 16;
    const uint32_t aOffL = smem_u32(pAl) + (wm + (lane & 15)) * RS + (lane >> 4) * 16;
    const int brow = wn + (lane & 7) + ((lane >> 4) & 1) * 8;
    const uint32_t bOffH = smem_u32(pWh) + brow * RS + ((lane >> 3) & 1) * 16;
    const uint32_t bOffL = smem_u32(pWl) + brow * RS + ((lane >> 3) & 1) * 16;

    float acc[2][8][4];
#pragma unroll
    for (int a = 0; a < 2; a++)
#pragma unroll
        for (int b = 0; b < 8; b++)
#pragma unroll
            for (int c = 0; c < 4; c++) acc[a][b][c] = 0.f;

    for (int k0 = 0; k0 < kH; k0 += 64) {
        __syncthreads();
#pragma unroll
        for (int i = 0; i < 4; i++) {
            int q = tid + i * 256;
            int row = q >> 3, c16 = q & 7;
            size_t ao = (size_t)(m0 + row) * kH + k0 + c16 * 8;
            size_t wo = (size_t)(n0 + row) * kH + k0 + c16 * 8;
            *(uint4*)(pAh + row * RS + c16 * 16) = *(const uint4*)(Ahi + ao);
            *(uint4*)(pAl + row * RS + c16 * 16) = *(const uint4*)(Alo + ao);
            *(uint4*)(pWh + row * RS + c16 * 16) = *(const uint4*)(Whi + wo);
            *(uint4*)(pWl + row * RS + c16 * 16) = *(const uint4*)(Wlo + wo);
        }
        __syncthreads();
#pragma unroll
        for (int kk = 0; kk < 4; kk++) {
            uint32_t ah0[4], ah1[4], al0[4], al1[4];
            LDSM4(ah0, aOffH + kk * 32);
            LDSM4(ah1, aOffH + 16 * RS + kk * 32);
            LDSM4(al0, aOffL + kk * 32);
            LDSM4(al1, aOffL + 16 * RS + kk * 32);
#pragma unroll
            for (int np = 0; np < 4; np++) {
                uint32_t bh[4], bl[4];
                LDSM4(bh, bOffH + np * 16 * RS + kk * 32);
                LDSM4(bl, bOffL + np * 16 * RS + kk * 32);
                HMMA(acc[0][np*2+0], ah0, bh+0); HMMA(acc[0][np*2+1], ah0, bh+2);
                HMMA(acc[1][np*2+0], ah1, bh+0); HMMA(acc[1][np*2+1], ah1, bh+2);
                HMMA(acc[0][np*2+0], ah0, bl+0); HMMA(acc[0][np*2+1], ah0, bl+2);
                HMMA(acc[1][np*2+0], ah1, bl+0); HMMA(acc[1][np*2+1], ah1, bl+2);
                HMMA(acc[0][np*2+0], al0, bh+0); HMMA(acc[0][np*2+1], al0, bh+2);
                HMMA(acc[1][np*2+0], al1, bh+0); HMMA(acc[1][np*2+1], al1, bh+2);
            }
        }
    }
    const int g = lane >> 2, tg2 = (lane & 3) * 2;
#pragma unroll
    for (int mf = 0; mf < 2; mf++)
#pragma unroll
        for (int nt = 0; nt < 8; nt++) {
            int m = m0 + wm + mf * 16 + g;
            int n = n0 + wn + nt * 8 + tg2;
            float b0 = bias[n], b1 = bias[n + 1];
            *(float2*)(C + (size_t)m * kH + n) =
                make_float2(acc[mf][nt][0] + b0, acc[mf][nt][1] + b1);
            *(float2*)(C + (size_t)(m + 8) * kH + n) =
                make_float2(acc[mf][nt][2] + b0, acc[mf][nt][3] + b1);
        }
}

// ---------------------------------------------------------------------------
// Single-pool balanced recurrence. 128 CTAs = 8 mt(128 cols) x 16 kc(64 k).
// Round r (0..512), every CTA:
//   stage h0[r-1] (shared by MMA-0 and MMA-ih) and h1[r-2]
//   r<512: MMA-0 (Whh0)        -> p0 -> reduce -> h0[r]
//   r>=1:  MMA-ih + MMA-hh     -> p1 -> reduce -> h1[r-1] (+output)
// All 3 W slices resident in SMEM. Flag dataflow, fan-in 16, no barriers.
// ---------------------------------------------------------------------------
#define RS2 144                     // 64 bf16 + 8 pad
#define SL  (128 * RS2)             // 18432: one W slice
#define HB2 (64 * RS2)              // 9216:  one h buffer
// W0h 0 | W0l SL | W1h 2SL | W1l 3SL | W2h 4SL | W2l 5SL | HAh | HAl | HBh | HBl
#define OHA (6 * SL)
#define RNN_SMEM (6 * SL + 4 * HB2)  // 147456

__device__ __forceinline__ void mma4(uint32_t aH, uint32_t aL,
                                     uint32_t bH, uint32_t bL, float (*acc)[4])
{
#pragma unroll
    for (int kk = 0; kk < 4; kk++) {
        uint32_t ah[4], al[4];
        LDSM4(ah, aH + kk * 32);
        LDSM4(al, aL + kk * 32);
#pragma unroll
        for (int np = 0; np < 4; np++) {
            uint32_t bh[4], bl[4];
            LDSM4(bh, bH + np * 16 * RS2 + kk * 32);
            LDSM4(bl, bL + np * 16 * RS2 + kk * 32);
            HMMA(acc[np*2+0], ah, bh+0); HMMA(acc[np*2+1], ah, bh+2);
            HMMA(acc[np*2+0], ah, bl+0); HMMA(acc[np*2+1], ah, bl+2);
            HMMA(acc[np*2+0], al, bh+0); HMMA(acc[np*2+1], al, bh+2);
        }
    }
}

__device__ __forceinline__ void stage_h64(char* dstH, char* dstL,
    const bf16* __restrict__ srcH, const bf16* __restrict__ srcL,
    int k0, int tid)
{
#pragma unroll
    for (int i = 0; i < 2; i++) {
        int q = tid + i * 256;                 // 0..511 (64 rows x 8 uint4)
        int row = q >> 3, c16 = q & 7;
        size_t o = (size_t)row * kH + k0 + c16 * 8;
        uint4 vh = __ldcg((const uint4*)(srcH + o));
        uint4 vl = __ldcg((const uint4*)(srcL + o));
        *(uint4*)(dstH + row * RS2 + c16 * 16) = vh;
        *(uint4*)(dstL + row * RS2 + c16 * 16) = vl;
    }
}

__global__ void __launch_bounds__(256) rnn_all(
    float* __restrict__ out_y, float* __restrict__ hfin0,
    float* __restrict__ hfin1)
{
    extern __shared__ char sm[];
    const int tid = threadIdx.x, lane = tid & 31, wid = tid >> 5;
    const int cta = blockIdx.x;
    const int mt = cta >> 4;                  // 0..7 (128 hidden cols)
    const int kc = cta & 15;                  // 0..15 (64-k chunk)
    const int h0c = mt * 128;
    const int k0 = kc * 64;
    const int bb0 = (wid & 3) * 16;
    const int hh0 = (wid >> 2) * 64;

    char* pHAh = sm + OHA;            char* pHAl = pHAh + HB2;
    char* pHBh = sm + OHA + 2 * HB2;  char* pHBl = pHBh + HB2;

    // ---- stage the 3 step-invariant W slices (hi+lo): Whh0, Wih1, Whh1 ----
    {
        const bf16* wsrc[6] = { g_s.Whi[1], g_s.Wlo[1], g_s.Whi[2],
                                g_s.Wlo[2], g_s.Whi[3], g_s.Wlo[3] };
#pragma unroll
        for (int sl = 0; sl < 6; sl++) {
            char* dst = sm + sl * SL;
            const bf16* src = wsrc[sl];
#pragma unroll
            for (int i = 0; i < 4; i++) {
                int q = tid + i * 256;         // 0..1023 (128 rows x 8 uint4)
                int row = q >> 3, c16 = q & 7;
                size_t o = (size_t)(h0c + row) * kH + k0 + c16 * 8;
                *(uint4*)(dst + row * RS2 + c16 * 16) = *(const uint4*)(src + o);
            }
        }
    }

    // ldmatrix bases
    const uint32_t aAH = smem_u32(pHAh) + ((bb0 + (lane & 15)) * RS2) + (lane >> 4) * 16;
    const uint32_t aAL = smem_u32(pHAl) + ((bb0 + (lane & 15)) * RS2) + (lane >> 4) * 16;
    const uint32_t aBH = smem_u32(pHBh) + ((bb0 + (lane & 15)) * RS2) + (lane >> 4) * 16;
    const uint32_t aBL = smem_u32(pHBl) + ((bb0 + (lane & 15)) * RS2) + (lane >> 4) * 16;
    const int brow = hh0 + (lane & 7) + ((lane >> 4) & 1) * 8;
    const uint32_t bW0H = smem_u32(sm + 0 * SL) + brow * RS2 + ((lane >> 3) & 1) * 16;
    const uint32_t bW0L = smem_u32(sm + 1 * SL) + brow * RS2 + ((lane >> 3) & 1) * 16;
    const uint32_t bW1H = smem_u32(sm + 2 * SL) + brow * RS2 + ((lane >> 3) & 1) * 16;
    const uint32_t bW1L = smem_u32(sm + 3 * SL) + brow * RS2 + ((lane >> 3) & 1) * 16;
    const uint32_t bW2H = smem_u32(sm + 4 * SL) + brow * RS2 + ((lane >> 3) & 1) * 16;
    const uint32_t bW2L = smem_u32(sm + 5 * SL) + brow * RS2 + ((lane >> 3) & 1) * 16;

    const int g = lane >> 2, tg2 = (lane & 3) * 2;
    const int ktile = kc >> 1;                // hidden tile containing our k-chunk

    // reduce ownership: cols [kc*8, kc*8+8) of tile mt; 2 elems/thread
    const int rb   = tid >> 2;                // batch row 0..63
    const int rcol = kc * 8 + (tid & 3) * 2;  // col within 128-tile
    const int gcol = h0c + rcol;
    const int gidx = rb * kH + gcol;

    for (int r = 0; r <= kT; r++) {
        const bool L0 = (r < kT);
        const bool L1 = (r >= 1);

        // ---- waits ----
        if (tid == 0) {
            if (r >= 1) spin_ge(&g_hf0[r - 1][ktile], 16);
            if (r >= 2) { spin_ge(&g_hf1[r - 2][ktile], 16);
                          spin_ge(&g_hf0[r - 2][mt], 16); }
            if (r >= 3) spin_ge(&g_hf1[r - 3][mt], 16);
        }
        __syncthreads();   // also: all warps done with prev round's LDSM

        // ---- stage h inputs ----
        stage_h64(pHAh, pHAl,
                  r ? g_h0hi + (size_t)(r - 1) * kBH : g_s.hinhi,
                  r ? g_h0lo + (size_t)(r - 1) * kBH : g_s.hinlo, k0, tid);
        if (L1)
            stage_h64(pHBh, pHBl,
                      r >= 2 ? g_h1hi + (size_t)(r - 2) * kBH : g_s.hinhi + kBH,
                      r >= 2 ? g_h1lo + (size_t)(r - 2) * kBH : g_s.hinlo + kBH,
                      k0, tid);
        float2 xv = make_float2(0.f, 0.f);
        if (L0) xv = __ldcg((const float2*)(g_s.X + (size_t)r * kBH + gidx));
        __syncthreads();

        // ---- MMA-0 (layer-0 hh) + partial store + flag ----
        if (L0) {
            float acc0[8][4];
#pragma unroll
            for (int a = 0; a < 8; a++)
#pragma unroll
                for (int c = 0; c < 4; c++) acc0[a][c] = 0.f;
            mma4(aAH, aAL, bW0H, bW0L, acc0);
            float* pp = &g_p0[r & 1][mt][kc][0];
            const int b = bb0 + g;
#pragma unroll
            for (int nt = 0; nt < 8; nt++) {
                int col = hh0 + nt * 8 + tg2;
                *(float2*)(pp + b * 128 + col) = make_float2(acc0[nt][0], acc0[nt][1]);
                *(float2*)(pp + (b + 8) * 128 + col) = make_float2(acc0[nt][2], acc0[nt][3]);
            }
            __syncthreads();
            if (tid == 0) { __threadfence(); atomicAdd(&g_pf0[r][mt], 1); }
        }

        // ---- MMA-ih (hides pf0 straggler skew) ----
        float acc1[8][4];
#pragma unroll
        for (int a = 0; a < 8; a++)
#pragma unroll
            for (int c = 0; c < 4; c++) acc1[a][c] = 0.f;
        if (L1) mma4(aAH, aAL, bW1H, bW1L, acc1);

        // ---- reduce-0: publish h0[r] early (serial-chain critical) ----
        if (L0) {
            if (tid == 0) spin_ge(&g_pf0[r][mt], 16);
            __syncthreads();
            float2 s = xv;
            const float* base = &g_p0[r & 1][mt][0][0];
#pragma unroll
            for (int rr = 0; rr < 16; rr++) {
                float2 p = __ldcg((const float2*)(base + rr * 8192 + rb * 128 + rcol));
                s.x += p.x; s.y += p.y;
            }
            float hx = tanhf(s.x), hy = tanhf(s.y);
            bf16 qx = __float2bfloat16(hx), qy = __float2bfloat16(hy);
            *(__nv_bfloat162*)(g_h0hi + (size_t)r * kBH + gidx) = __halves2bfloat162(qx, qy);
            *(__nv_bfloat162*)(g_h0lo + (size_t)r * kBH + gidx) = __halves2bfloat162(
                __float2bfloat16(hx - __bfloat162float(qx)),
                __float2bfloat16(hy - __bfloat162float(qy)));
            if (r == kT - 1) *(float2*)(hfin0 + gidx) = make_float2(hx, hy);
            __syncthreads();
            if (tid == 0) { __threadfence(); atomicAdd(&g_hf0[r][mt], 1); }
        }

        // ---- MMA-hh + partial + reduce-1: h1[r-1] ----
        if (L1) {
            mma4(aBH, aBL, bW2H, bW2L, acc1);
            float* pp = &g_p1[(r - 1) & 1][mt][kc][0];
            const int b = bb0 + g;
#pragma unroll
            for (int nt = 0; nt < 8; nt++) {
                int col = hh0 + nt * 8 + tg2;
                *(float2*)(pp + b * 128 + col) = make_float2(acc1[nt][0], acc1[nt][1]);
                *(float2*)(pp + (b + 8) * 128 + col) = make_float2(acc1[nt][2], acc1[nt][3]);
            }
            __syncthreads();
            if (tid == 0) { __threadfence(); atomicAdd(&g_pf1[r - 1][mt], 1);
                            spin_ge(&g_pf1[r - 1][mt], 16); }
            __syncthreads();

            float2 s = *(const float2*)(g_s.bias[1] + gcol);
            const float* base = &g_p1[(r - 1) & 1][mt][0][0];
#pragma unroll
            for (int rr = 0; rr < 16; rr++) {
                float2 p = __ldcg((const float2*)(base + rr * 8192 + rb * 128 + rcol));
                s.x += p.x; s.y += p.y;
            }
            float hx = tanhf(s.x), hy = tanhf(s.y);
            *(float2*)(out_y + (size_t)(r - 1) * kBH + gidx) = make_float2(hx, hy);
            bf16 qx = __float2bfloat16(hx), qy = __float2bfloat16(hy);
            *(__nv_bfloat162*)(g_h1hi + (size_t)(r - 1) * kBH + gidx) = __halves2bfloat162(qx, qy);
            *(__nv_bfloat162*)(g_h1lo + (size_t)(r - 1) * kBH + gidx) = __halves2bfloat162(
                __float2bfloat16(hx - __bfloat162float(qx)),
                __float2bfloat16(hy - __bfloat162float(qy)));
            if (r == kT) *(float2*)(hfin1 + gidx) = make_float2(hx, hy);
            __syncthreads();
            if (tid == 0) { __threadfence(); atomicAdd(&g_hf1[r - 1][mt], 1); }
        }
    }
}

// ---------------------------------------------------------------------------
// Launch
// ---------------------------------------------------------------------------
extern "C" void kernel_launch(void* const* d_in, const int* in_sizes, int n_in,
                              void* d_out, int out_size)
{
    const float* input = (const float*)d_in[0];
    const float* h_0   = (const float*)d_in[1];
    const float* W_ih0 = (const float*)d_in[2];
    const float* b_ih0 = (const float*)d_in[3];
    const float* W_hh0 = (const float*)d_in[4];
    const float* b_hh0 = (const float*)d_in[5];
    const float* W_ih1 = (const float*)d_in[6];
    const float* b_ih1 = (const float*)d_in[7];
    const float* W_hh1 = (const float*)d_in[8];
    const float* b_hh1 = (const float*)d_in[9];
    float* out = (float*)d_out;

    Scratch* s = nullptr;
    cudaGetSymbolAddress((void**)&s, g_s);

    const int gemm_smem = 4 * 128 * 144;
    cudaFuncSetAttribute(gemm_mma, cudaFuncAttributeMaxDynamicSharedMemorySize, gemm_smem);
    cudaFuncSetAttribute(rnn_all, cudaFuncAttributeMaxDynamicSharedMemorySize, RNN_SMEM);

    zero_flags<<<16, 256>>>();
    split_pair<<<2048, 256>>>(input, s->Ahi, s->Alo, kTBH / 4);
    split_pair<<<1024, 256>>>(W_ih0, s->Whi[0], s->Wlo[0], kH * kH / 4);
    split_pair<<<1024, 256>>>(W_hh0, s->Whi[1], s->Wlo[1], kH * kH / 4);
    split_pair<<<1024, 256>>>(W_ih1, s->Whi[2], s->Wlo[2], kH * kH / 4);
    split_pair<<<1024, 256>>>(W_hh1, s->Whi[3], s->Wlo[3], kH * kH / 4);
    split_pair<<<128, 256>>>(h_0, s->hinhi, s->hinlo, 2 * kBH / 4);
    bias2<<<4, 256>>>(b_ih0, b_hh0, b_ih1, b_hh1, s->bias[0], s->bias[1]);

    dim3 ggrid(kH / 128, kTB / 128);
    gemm_mma<<<ggrid, 256, gemm_smem>>>(s->Ahi, s->Alo, s->Whi[0], s->Wlo[0],
                                        s->bias[0], s->X);

    rnn_all<<<128, 256, RNN_SMEM>>>(out, out + (size_t)kTBH,
                                    out + (size_t)kTBH + kBH);
}

// round 13
// speedup vs baseline: 1.1301x; 1.1301x over previous
#include <cuda_runtime.h>
#include <cuda_bf16.h>
#include <math.h>
#include <stdint.h>

#define kT   512
#define kB   64
#define kH   1024
#define kBH  65536
#define kTB  32768
#define kTBH 33554432

typedef __nv_bfloat16 bf16;

// ---------------------------------------------------------------------------
// Scratch (device globals; allocations forbidden)
// ---------------------------------------------------------------------------
struct __align__(16) Scratch {
    float X[kTBH];                        // X0 = input @ W_ih0^T + biases
    bf16  Ahi[kTBH], Alo[kTBH];           // split input
    bf16  Whi[4][kH * kH];                // split weights: ih0, hh0, ih1, hh1
    bf16  Wlo[4][kH * kH];
    float bias[2][kH];
    bf16  hinhi[2 * kBH], hinlo[2 * kBH]; // split initial h (layer0, layer1)
};
__device__ Scratch g_s;

// write-once hidden histories (bf16 split)
__device__ bf16 g_h0hi[kTBH], g_h0lo[kTBH];
__device__ bf16 g_h1hi[kTBH], g_h1lo[kTBH];

// k-split partials, 4-deep slots: [slot][mt][kc][64*128]
__device__ float g_p0[4][8][16][64 * 128];
__device__ float g_p1[4][8][16][64 * 128];

// dataflow flags (monotonic counters; fan-in 16)
__device__ int g_pf0[kT][8], g_pf1[kT][8];
__device__ int g_hf0[kT][8], g_hf1[kT][8];

// ---------------------------------------------------------------------------
// Warp MMA primitives (baseline ISA: HMMA + ldmatrix)
// ---------------------------------------------------------------------------
__device__ __forceinline__ uint32_t smem_u32(const void* p) {
    uint32_t r;
    asm("{ .reg .u64 t; cvta.to.shared.u64 t, %1; cvt.u32.u64 %0, t; }" : "=r"(r) : "l"(p));
    return r;
}
#define LDSM4(r, addr)                                                        \
    asm volatile("ldmatrix.sync.aligned.m8n8.x4.shared.b16 {%0,%1,%2,%3}, [%4];" \
        : "=r"((r)[0]), "=r"((r)[1]), "=r"((r)[2]), "=r"((r)[3]) : "r"(addr))
#define HMMA(d, a, b)                                                         \
    asm volatile("mma.sync.aligned.m16n8k16.row.col.f32.bf16.bf16.f32 "       \
        "{%0,%1,%2,%3}, {%4,%5,%6,%7}, {%8,%9}, {%0,%1,%2,%3};"               \
        : "+f"((d)[0]), "+f"((d)[1]), "+f"((d)[2]), "+f"((d)[3])              \
        : "r"((a)[0]), "r"((a)[1]), "r"((a)[2]), "r"((a)[3]),                 \
          "r"((b)[0]), "r"((b)[1]))

#define BARA() asm volatile("bar.sync 1, 128;" ::: "memory")
#define BARB() asm volatile("bar.sync 2, 128;" ::: "memory")

__device__ __forceinline__ void spin_ge(const int* f, int n) {
    while (true) {
        int v;
        asm volatile("ld.acquire.gpu.global.s32 %0, [%1];" : "=r"(v) : "l"(f));
        if (v >= n) break;
        __nanosleep(20);
    }
}

// ---------------------------------------------------------------------------
// prep kernels
// ---------------------------------------------------------------------------
__global__ void split_pair(const float* __restrict__ s, bf16* __restrict__ hi,
                           bf16* __restrict__ lo, int n4) {
    int stride = gridDim.x * blockDim.x;
    for (int i = blockIdx.x * blockDim.x + threadIdx.x; i < n4; i += stride) {
        float4 v = ((const float4*)s)[i];
        bf16 h0 = __float2bfloat16(v.x), h1 = __float2bfloat16(v.y);
        bf16 h2 = __float2bfloat16(v.z), h3 = __float2bfloat16(v.w);
        ((__nv_bfloat162*)hi)[i * 2 + 0] = __halves2bfloat162(h0, h1);
        ((__nv_bfloat162*)hi)[i * 2 + 1] = __halves2bfloat162(h2, h3);
        ((__nv_bfloat162*)lo)[i * 2 + 0] = __halves2bfloat162(
            __float2bfloat16(v.x - __bfloat162float(h0)),
            __float2bfloat16(v.y - __bfloat162float(h1)));
        ((__nv_bfloat162*)lo)[i * 2 + 1] = __halves2bfloat162(
            __float2bfloat16(v.z - __bfloat162float(h2)),
            __float2bfloat16(v.w - __bfloat162float(h3)));
    }
}
__global__ void bias2(const float* a, const float* b, const float* c,
                      const float* d, float* o0, float* o1) {
    int i = blockIdx.x * 256 + threadIdx.x;
    if (i < kH) { o0[i] = a[i] + b[i]; o1[i] = c[i] + d[i]; }
}
__global__ void zero_flags() {
    int i = blockIdx.x * 256 + threadIdx.x;
    if (i < kT * 8) {
        ((int*)g_pf0)[i] = 0; ((int*)g_pf1)[i] = 0;
        ((int*)g_hf0)[i] = 0; ((int*)g_hf1)[i] = 0;
    }
}

// ---------------------------------------------------------------------------
// Big HMMA GEMM for X0 (proven R4 kernel, unchanged)
// ---------------------------------------------------------------------------
__global__ void __launch_bounds__(256) gemm_mma(
    const bf16* __restrict__ Ahi, const bf16* __restrict__ Alo,
    const bf16* __restrict__ Whi, const bf16* __restrict__ Wlo,
    const float* __restrict__ bias, float* __restrict__ C)
{
    extern __shared__ char sm[];
    enum { RS = 144, BUF = 128 * 144 };
    char* pAh = sm;            char* pAl = sm + BUF;
    char* pWh = sm + 2 * BUF;  char* pWl = sm + 3 * BUF;

    const int tid = threadIdx.x, lane = tid & 31, wid = tid >> 5;
    const int n0 = blockIdx.x * 128, m0 = blockIdx.y * 128;
    const int wm = (wid >> 1) * 32, wn = (wid & 1) * 64;

    const uint32_t aOffH = smem_u32(pAh) + (wm + (lane & 15)) * RS + (lane >> 4) * 16;
    const uint32_t aOffL = smem_u32(pAl) + (wm + (lane & 15)) * RS + (lane >> 4) * 16;
    const int brow = wn + (lane & 7) + ((lane >> 4) & 1) * 8;
    const uint32_t bOffH = smem_u32(pWh) + brow * RS + ((lane >> 3) & 1) * 16;
    const uint32_t bOffL = smem_u32(pWl) + brow * RS + ((lane >> 3) & 1) * 16;

    float acc[2][8][4];
#pragma unroll
    for (int a = 0; a < 2; a++)
#pragma unroll
        for (int b = 0; b < 8; b++)
#pragma unroll
            for (int c = 0; c < 4; c++) acc[a][b][c] = 0.f;

    for (int k0 = 0; k0 < kH; k0 += 64) {
        __syncthreads();
#pragma unroll
        for (int i = 0; i < 4; i++) {
            int q = tid + i * 256;
            int row = q >> 3, c16 = q & 7;
            size_t ao = (size_t)(m0 + row) * kH + k0 + c16 * 8;
            size_t wo = (size_t)(n0 + row) * kH + k0 + c16 * 8;
            *(uint4*)(pAh + row * RS + c16 * 16) = *(const uint4*)(Ahi + ao);
            *(uint4*)(pAl + row * RS + c16 * 16) = *(const uint4*)(Alo + ao);
            *(uint4*)(pWh + row * RS + c16 * 16) = *(const uint4*)(Whi + wo);
            *(uint4*)(pWl + row * RS + c16 * 16) = *(const uint4*)(Wlo + wo);
        }
        __syncthreads();
#pragma unroll
        for (int kk = 0; kk < 4; kk++) {
            uint32_t ah0[4], ah1[4], al0[4], al1[4];
            LDSM4(ah0, aOffH + kk * 32);
            LDSM4(ah1, aOffH + 16 * RS + kk * 32);
            LDSM4(al0, aOffL + kk * 32);
            LDSM4(al1, aOffL + 16 * RS + kk * 32);
#pragma unroll
            for (int np = 0; np < 4; np++) {
                uint32_t bh[4], bl[4];
                LDSM4(bh, bOffH + np * 16 * RS + kk * 32);
                LDSM4(bl, bOffL + np * 16 * RS + kk * 32);
                HMMA(acc[0][np*2+0], ah0, bh+0); HMMA(acc[0][np*2+1], ah0, bh+2);
                HMMA(acc[1][np*2+0], ah1, bh+0); HMMA(acc[1][np*2+1], ah1, bh+2);
                HMMA(acc[0][np*2+0], ah0, bl+0); HMMA(acc[0][np*2+1], ah0, bl+2);
                HMMA(acc[1][np*2+0], ah1, bl+0); HMMA(acc[1][np*2+1], ah1, bl+2);
                HMMA(acc[0][np*2+0], al0, bh+0); HMMA(acc[0][np*2+1], al0, bh+2);
                HMMA(acc[1][np*2+0], al1, bh+0); HMMA(acc[1][np*2+1], al1, bh+2);
            }
        }
    }
    const int g = lane >> 2, tg2 = (lane & 3) * 2;
#pragma unroll
    for (int mf = 0; mf < 2; mf++)
#pragma unroll
        for (int nt = 0; nt < 8; nt++) {
            int m = m0 + wm + mf * 16 + g;
            int n = n0 + wn + nt * 8 + tg2;
            float b0 = bias[n], b1 = bias[n + 1];
            *(float2*)(C + (size_t)m * kH + n) =
                make_float2(acc[mf][nt][0] + b0, acc[mf][nt][1] + b1);
            *(float2*)(C + (size_t)(m + 8) * kH + n) =
                make_float2(acc[mf][nt][2] + b0, acc[mf][nt][3] + b1);
        }
}

// ---------------------------------------------------------------------------
// Warp-specialized fused recurrence. 128 CTAs = 8 mt(128 cols) x 16 kc(64 k).
// Warps 0-3 (group A): layer-0 chain.  Warps 4-7 (group B): layer-1 chain.
// Independent flag-driven loops; A never waits on B. Named barriers per group.
//   A round t: h0[t] = tanh(X0[t] + h0[t-1] @ Whh0^T)
//   B round t: h1[t] = tanh(b1 + h0[t] @ Wih1^T + h1[t-1] @ Whh1^T)
// ---------------------------------------------------------------------------
#define RS2 144
#define SL  (128 * RS2)               // 18432
#define HBf (64 * RS2)                // 9216
#define OHA  (6 * SL)                 // HA hi/lo (group A)
#define OHB0 (6 * SL + 2 * HBf)       // HB0 hi/lo (group B: h0[t])
#define OHB1 (6 * SL + 4 * HBf)       // HB1 hi/lo (group B: h1[t-1])
#define RNN_SMEM (6 * SL + 6 * HBf)   // 165888

__device__ __forceinline__ void stage128(char* dstH, char* dstL,
    const bf16* __restrict__ srcH, const bf16* __restrict__ srcL,
    int k0, int gtid)
{
#pragma unroll
    for (int i = 0; i < 4; i++) {
        int q = gtid + i * 128;                // 0..511 (64 rows x 8 uint4)
        int row = q >> 3, c16 = q & 7;
        size_t o = (size_t)row * kH + k0 + c16 * 8;
        uint4 vh = __ldcg((const uint4*)(srcH + o));
        uint4 vl = __ldcg((const uint4*)(srcL + o));
        *(uint4*)(dstH + row * RS2 + c16 * 16) = vh;
        *(uint4*)(dstL + row * RS2 + c16 * 16) = vl;
    }
}

__global__ void __launch_bounds__(256) rnn_ws(
    float* __restrict__ out_y, float* __restrict__ hfin0,
    float* __restrict__ hfin1)
{
    extern __shared__ char sm[];
    const int tid = threadIdx.x, lane = tid & 31, wid = tid >> 5;
    const int cta = blockIdx.x;
    const int mt = cta >> 4;                  // 0..7 (128 hidden cols)
    const int kc = cta & 15;                  // 0..15 (64-k chunk)
    const int h0c = mt * 128;
    const int k0 = kc * 64;
    const int ktile = kc >> 1;                // tile that produces our k-range
    const int group = wid >> 2;               // 0 = layer0, 1 = layer1
    const int gw = wid & 3;                   // warp within group
    const int gtid = tid & 127;

    // ---- cooperative staging of 6 step-invariant W slices ----
    {
        const bf16* wsrc[6] = { g_s.Whi[1], g_s.Wlo[1], g_s.Whi[2],
                                g_s.Wlo[2], g_s.Whi[3], g_s.Wlo[3] };
#pragma unroll
        for (int sl = 0; sl < 6; sl++) {
            char* dst = sm + sl * SL;
            const bf16* src = wsrc[sl];
#pragma unroll
            for (int i = 0; i < 4; i++) {
                int q = tid + i * 256;         // 0..1023 (128 rows x 8 uint4)
                int row = q >> 3, c16 = q & 7;
                size_t o = (size_t)(h0c + row) * kH + k0 + c16 * 8;
                *(uint4*)(dst + row * RS2 + c16 * 16) = *(const uint4*)(src + o);
            }
        }
    }
    __syncthreads();    // LAST full-CTA sync; groups diverge permanently below

    // fragment address bases
    const int bb = gw * 16;                           // warp's 16 batch rows
    const int browB = (lane & 7) + ((lane >> 4) & 1) * 8;
    const uint32_t bsel = ((lane >> 3) & 1) * 16;
    const uint32_t asel = (lane >> 4) * 16;
    const uint32_t arow = (bb + (lane & 15)) * RS2;

    const uint32_t bW0H = smem_u32(sm + 0 * SL) + browB * RS2 + bsel;
    const uint32_t bW0L = smem_u32(sm + 1 * SL) + browB * RS2 + bsel;
    const uint32_t bW1H = smem_u32(sm + 2 * SL) + browB * RS2 + bsel;
    const uint32_t bW1L = smem_u32(sm + 3 * SL) + browB * RS2 + bsel;
    const uint32_t bW2H = smem_u32(sm + 4 * SL) + browB * RS2 + bsel;
    const uint32_t bW2L = smem_u32(sm + 5 * SL) + browB * RS2 + bsel;

    const int g = lane >> 2, tg2 = (lane & 3) * 2;

    // reduce/publish ownership: 128 threads cover 64 rows x 8 cols (float4)
    const int rb   = gtid >> 1;                        // batch row
    const int rc4  = kc * 8 + (gtid & 1) * 4;          // col within 128-tile
    const int gcol = h0c + rc4;
    const int gidx = rb * kH + gcol;

    if (group == 0) {
        // ================= GROUP A: layer-0 serial chain =================
        char* pHAh = sm + OHA;  char* pHAl = pHAh + HBf;
        const uint32_t aH = smem_u32(pHAh) + arow + asel;
        const uint32_t aL = smem_u32(pHAl) + arow + asel;

        for (int t = 0; t < kT; t++) {
            if (gtid == 0) {
                if (t >= 1) spin_ge(&g_hf0[t - 1][ktile], 16);
                if (t >= 4) spin_ge(&g_hf0[t - 4][mt], 16);   // p0 slot guard
            }
            BARA();
            stage128(pHAh, pHAl,
                     t ? g_h0hi + (size_t)(t - 1) * kBH : g_s.hinhi,
                     t ? g_h0lo + (size_t)(t - 1) * kBH : g_s.hinlo, k0, gtid);
            float4 xv = __ldcg((const float4*)(g_s.X + (size_t)t * kBH + gidx));
            BARA();

            float acc[16][4];
#pragma unroll
            for (int a = 0; a < 16; a++)
#pragma unroll
                for (int c = 0; c < 4; c++) acc[a][c] = 0.f;
#pragma unroll
            for (int kk = 0; kk < 4; kk++) {
                uint32_t ah[4], al[4];
                LDSM4(ah, aH + kk * 32);
                LDSM4(al, aL + kk * 32);
#pragma unroll
                for (int np = 0; np < 8; np++) {
                    uint32_t bh[4], bl[4];
                    LDSM4(bh, bW0H + np * 16 * RS2 + kk * 32);
                    LDSM4(bl, bW0L + np * 16 * RS2 + kk * 32);
                    HMMA(acc[np*2+0], ah, bh+0); HMMA(acc[np*2+1], ah, bh+2);
                    HMMA(acc[np*2+0], ah, bl+0); HMMA(acc[np*2+1], ah, bl+2);
                    HMMA(acc[np*2+0], al, bh+0); HMMA(acc[np*2+1], al, bh+2);
                }
            }

            float* pp = &g_p0[t & 3][mt][kc][0];
            const int b = bb + g;
#pragma unroll
            for (int nt = 0; nt < 16; nt++) {
                int col = nt * 8 + tg2;
                *(float2*)(pp + b * 128 + col) = make_float2(acc[nt][0], acc[nt][1]);
                *(float2*)(pp + (b + 8) * 128 + col) = make_float2(acc[nt][2], acc[nt][3]);
            }
            BARA();
            if (gtid == 0) {
                __threadfence(); atomicAdd(&g_pf0[t][mt], 1);
                spin_ge(&g_pf0[t][mt], 16);
            }
            BARA();

            float4 s = xv;
            const float* base = &g_p0[t & 3][mt][0][0];
#pragma unroll
            for (int rr = 0; rr < 16; rr++) {
                float4 p = __ldcg((const float4*)(base + rr * 8192 + rb * 128 + rc4));
                s.x += p.x; s.y += p.y; s.z += p.z; s.w += p.w;
            }
            float4 h4 = make_float4(tanhf(s.x), tanhf(s.y), tanhf(s.z), tanhf(s.w));
            bf16 q0 = __float2bfloat16(h4.x), q1 = __float2bfloat16(h4.y);
            bf16 q2 = __float2bfloat16(h4.z), q3 = __float2bfloat16(h4.w);
            bf16* dh = g_h0hi + (size_t)t * kBH + gidx;
            bf16* dl = g_h0lo + (size_t)t * kBH + gidx;
            ((__nv_bfloat162*)dh)[0] = __halves2bfloat162(q0, q1);
            ((__nv_bfloat162*)dh)[1] = __halves2bfloat162(q2, q3);
            ((__nv_bfloat162*)dl)[0] = __halves2bfloat162(
                __float2bfloat16(h4.x - __bfloat162float(q0)),
                __float2bfloat16(h4.y - __bfloat162float(q1)));
            ((__nv_bfloat162*)dl)[1] = __halves2bfloat162(
                __float2bfloat16(h4.z - __bfloat162float(q2)),
                __float2bfloat16(h4.w - __bfloat162float(q3)));
            if (t == kT - 1) *(float4*)(hfin0 + gidx) = h4;
            BARA();
            if (gtid == 0) { __threadfence(); atomicAdd(&g_hf0[t][mt], 1); }
        }
    } else {
        // ================= GROUP B: layer-1 trailing chain =================
        char* pB0h = sm + OHB0;  char* pB0l = pB0h + HBf;
        char* pB1h = sm + OHB1;  char* pB1l = pB1h + HBf;
        const uint32_t a0H = smem_u32(pB0h) + arow + asel;
        const uint32_t a0L = smem_u32(pB0l) + arow + asel;
        const uint32_t a1H = smem_u32(pB1h) + arow + asel;
        const uint32_t a1L = smem_u32(pB1l) + arow + asel;
        const float2 bv0 = *(const float2*)(g_s.bias[1] + gcol);
        const float2 bv1 = *(const float2*)(g_s.bias[1] + gcol + 2);

        for (int t = 0; t < kT; t++) {
            if (gtid == 0) {
                spin_ge(&g_hf0[t][ktile], 16);                 // h0[t]
                if (t >= 1) spin_ge(&g_hf1[t - 1][ktile], 16); // h1[t-1]
                if (t >= 4) spin_ge(&g_hf1[t - 4][mt], 16);    // p1 slot guard
            }
            BARB();
            stage128(pB0h, pB0l, g_h0hi + (size_t)t * kBH,
                                 g_h0lo + (size_t)t * kBH, k0, gtid);
            stage128(pB1h, pB1l,
                     t ? g_h1hi + (size_t)(t - 1) * kBH : g_s.hinhi + kBH,
                     t ? g_h1lo + (size_t)(t - 1) * kBH : g_s.hinlo + kBH,
                     k0, gtid);
            BARB();

            float acc[16][4];
#pragma unroll
            for (int a = 0; a < 16; a++)
#pragma unroll
                for (int c = 0; c < 4; c++) acc[a][c] = 0.f;
#pragma unroll
            for (int kk = 0; kk < 4; kk++) {
                uint32_t x0h[4], x0l[4], x1h[4], x1l[4];
                LDSM4(x0h, a0H + kk * 32);
                LDSM4(x0l, a0L + kk * 32);
                LDSM4(x1h, a1H + kk * 32);
                LDSM4(x1l, a1L + kk * 32);
#pragma unroll
                for (int np = 0; np < 8; np++) {
                    uint32_t w1h[4], w1l[4], w2h[4], w2l[4];
                    LDSM4(w1h, bW1H + np * 16 * RS2 + kk * 32);
                    LDSM4(w1l, bW1L + np * 16 * RS2 + kk * 32);
                    LDSM4(w2h, bW2H + np * 16 * RS2 + kk * 32);
                    LDSM4(w2l, bW2L + np * 16 * RS2 + kk * 32);
                    HMMA(acc[np*2+0], x0h, w1h+0); HMMA(acc[np*2+1], x0h, w1h+2);
                    HMMA(acc[np*2+0], x1h, w2h+0); HMMA(acc[np*2+1], x1h, w2h+2);
                    HMMA(acc[np*2+0], x0h, w1l+0); HMMA(acc[np*2+1], x0h, w1l+2);
                    HMMA(acc[np*2+0], x1h, w2l+0); HMMA(acc[np*2+1], x1h, w2l+2);
                    HMMA(acc[np*2+0], x0l, w1h+0); HMMA(acc[np*2+1], x0l, w1h+2);
                    HMMA(acc[np*2+0], x1l, w2h+0); HMMA(acc[np*2+1], x1l, w2h+2);
                }
            }

            float* pp = &g_p1[t & 3][mt][kc][0];
            const int b = bb + g;
#pragma unroll
            for (int nt = 0; nt < 16; nt++) {
                int col = nt * 8 + tg2;
                *(float2*)(pp + b * 128 + col) = make_float2(acc[nt][0], acc[nt][1]);
                *(float2*)(pp + (b + 8) * 128 + col) = make_float2(acc[nt][2], acc[nt][3]);
            }
            BARB();
            if (gtid == 0) {
                __threadfence(); atomicAdd(&g_pf1[t][mt], 1);
                spin_ge(&g_pf1[t][mt], 16);
            }
            BARB();

            float4 s = make_float4(bv0.x, bv0.y, bv1.x, bv1.y);
            const float* base = &g_p1[t & 3][mt][0][0];
#pragma unroll
            for (int rr = 0; rr < 16; rr++) {
                float4 p = __ldcg((const float4*)(base + rr * 8192 + rb * 128 + rc4));
                s.x += p.x; s.y += p.y; s.z += p.z; s.w += p.w;
            }
            float4 h4 = make_float4(tanhf(s.x), tanhf(s.y), tanhf(s.z), tanhf(s.w));
            *(float4*)(out_y + (size_t)t * kBH + gidx) = h4;
            bf16 q0 = __float2bfloat16(h4.x), q1 = __float2bfloat16(h4.y);
            bf16 q2 = __float2bfloat16(h4.z), q3 = __float2bfloat16(h4.w);
            bf16* dh = g_h1hi + (size_t)t * kBH + gidx;
            bf16* dl = g_h1lo + (size_t)t * kBH + gidx;
            ((__nv_bfloat162*)dh)[0] = __halves2bfloat162(q0, q1);
            ((__nv_bfloat162*)dh)[1] = __halves2bfloat162(q2, q3);
            ((__nv_bfloat162*)dl)[0] = __halves2bfloat162(
                __float2bfloat16(h4.x - __bfloat162float(q0)),
                __float2bfloat16(h4.y - __bfloat162float(q1)));
            ((__nv_bfloat162*)dl)[1] = __halves2bfloat162(
                __float2bfloat16(h4.z - __bfloat162float(q2)),
                __float2bfloat16(h4.w - __bfloat162float(q3)));
            if (t == kT - 1) *(float4*)(hfin1 + gidx) = h4;
            BARB();
            if (gtid == 0) { __threadfence(); atomicAdd(&g_hf1[t][mt], 1); }
        }
    }
}

// ---------------------------------------------------------------------------
// Launch
// ---------------------------------------------------------------------------
extern "C" void kernel_launch(void* const* d_in, const int* in_sizes, int n_in,
                              void* d_out, int out_size)
{
    const float* input = (const float*)d_in[0];
    const float* h_0   = (const float*)d_in[1];
    const float* W_ih0 = (const float*)d_in[2];
    const float* b_ih0 = (const float*)d_in[3];
    const float* W_hh0 = (const float*)d_in[4];
    const float* b_hh0 = (const float*)d_in[5];
    const float* W_ih1 = (const float*)d_in[6];
    const float* b_ih1 = (const float*)d_in[7];
    const float* W_hh1 = (const float*)d_in[8];
    const float* b_hh1 = (const float*)d_in[9];
    float* out = (float*)d_out;

    Scratch* s = nullptr;
    cudaGetSymbolAddress((void**)&s, g_s);

    const int gemm_smem = 4 * 128 * 144;
    cudaFuncSetAttribute(gemm_mma, cudaFuncAttributeMaxDynamicSharedMemorySize, gemm_smem);
    cudaFuncSetAttribute(rnn_ws, cudaFuncAttributeMaxDynamicSharedMemorySize, RNN_SMEM);

    zero_flags<<<16, 256>>>();
    split_pair<<<2048, 256>>>(input, s->Ahi, s->Alo, kTBH / 4);
    split_pair<<<1024, 256>>>(W_ih0, s->Whi[0], s->Wlo[0], kH * kH / 4);
    split_pair<<<1024, 256>>>(W_hh0, s->Whi[1], s->Wlo[1], kH * kH / 4);
    split_pair<<<1024, 256>>>(W_ih1, s->Whi[2], s->Wlo[2], kH * kH / 4);
    split_pair<<<1024, 256>>>(W_hh1, s->Whi[3], s->Wlo[3], kH * kH / 4);
    split_pair<<<128, 256>>>(h_0, s->hinhi, s->hinlo, 2 * kBH / 4);
    bias2<<<4, 256>>>(b_ih0, b_hh0, b_ih1, b_hh1, s->bias[0], s->bias[1]);

    dim3 ggrid(kH / 128, kTB / 128);
    gemm_mma<<<ggrid, 256, gemm_smem>>>(s->Ahi, s->Alo, s->Whi[0], s->Wlo[0],
                                        s->bias[0], s->X);

    rnn_ws<<<128, 256, RNN_SMEM>>>(out, out + (size_t)kTBH,
                                   out + (size_t)kTBH + kBH);
}

// round 14
// speedup vs baseline: 1.3933x; 1.2329x over previous
#include <cuda_runtime.h>
#include <cuda_fp16.h>
#include <math.h>
#include <stdint.h>

#define kT   512
#define kB   64
#define kH   1024
#define kBH  65536
#define kTB  32768
#define kTBH 33554432

// ---------------------------------------------------------------------------
// Scratch (device globals; allocations forbidden)
// ---------------------------------------------------------------------------
struct __align__(16) Scratch {
    float  X[kTBH];                      // X0 = input @ W_ih0^T + biases (fp32)
    __half Ah[kTBH];                     // input as fp16 (single)
    __half Whi[4][kH * kH];              // W hi: ih0, hh0, ih1, hh1
    __half Wlo[4][kH * kH];              // W lo (fp16 residual)
    float  bias[2][kH];
    __half hin[2 * kBH];                 // initial h (fp16 single)
};
__device__ Scratch g_s;

// write-once hidden histories (fp16 single — no lo needed in x2 scheme)
__device__ __half g_h0[kTBH], g_h1[kTBH];

// k-split partials, 4-deep slots: [slot][mt][kc][64*128]
__device__ float g_p0[4][8][16][64 * 128];
__device__ float g_p1[4][8][16][64 * 128];

// dataflow flags (monotonic counters; fan-in 16)
__device__ int g_pf0[kT][8], g_pf1[kT][8];
__device__ int g_hf0[kT][8], g_hf1[kT][8];

// ---------------------------------------------------------------------------
// Warp MMA primitives (baseline ISA: fp16 HMMA + ldmatrix)
// ---------------------------------------------------------------------------
__device__ __forceinline__ uint32_t smem_u32(const void* p) {
    uint32_t r;
    asm("{ .reg .u64 t; cvta.to.shared.u64 t, %1; cvt.u32.u64 %0, t; }" : "=r"(r) : "l"(p));
    return r;
}
#define LDSM4(r, addr)                                                        \
    asm volatile("ldmatrix.sync.aligned.m8n8.x4.shared.b16 {%0,%1,%2,%3}, [%4];" \
        : "=r"((r)[0]), "=r"((r)[1]), "=r"((r)[2]), "=r"((r)[3]) : "r"(addr))
#define HMMA(d, a, b)                                                         \
    asm volatile("mma.sync.aligned.m16n8k16.row.col.f32.f16.f16.f32 "         \
        "{%0,%1,%2,%3}, {%4,%5,%6,%7}, {%8,%9}, {%0,%1,%2,%3};"               \
        : "+f"((d)[0]), "+f"((d)[1]), "+f"((d)[2]), "+f"((d)[3])              \
        : "r"((a)[0]), "r"((a)[1]), "r"((a)[2]), "r"((a)[3]),                 \
          "r"((b)[0]), "r"((b)[1]))

#define BARA() asm volatile("bar.sync 1, 256;" ::: "memory")
#define BARB() asm volatile("bar.sync 2, 256;" ::: "memory")

__device__ __forceinline__ void spin_ge(const int* f, int n) {
    while (true) {
        int v;
        asm volatile("ld.acquire.gpu.global.s32 %0, [%1];" : "=r"(v) : "l"(f));
        if (v >= n) break;
        __nanosleep(20);
    }
}

// ---------------------------------------------------------------------------
// prep kernels
// ---------------------------------------------------------------------------
__global__ void cvt_half(const float* __restrict__ s, __half* __restrict__ d, int n4) {
    int stride = gridDim.x * blockDim.x;
    for (int i = blockIdx.x * blockDim.x + threadIdx.x; i < n4; i += stride) {
        float4 v = ((const float4*)s)[i];
        __half2* o = (__half2*)d + i * 2;
        o[0] = __floats2half2_rn(v.x, v.y);
        o[1] = __floats2half2_rn(v.z, v.w);
    }
}
__global__ void split_half(const float* __restrict__ s, __half* __restrict__ hi,
                           __half* __restrict__ lo, int n4) {
    int stride = gridDim.x * blockDim.x;
    for (int i = blockIdx.x * blockDim.x + threadIdx.x; i < n4; i += stride) {
        float4 v = ((const float4*)s)[i];
        __half h0 = __float2half(v.x), h1 = __float2half(v.y);
        __half h2 = __float2half(v.z), h3 = __float2half(v.w);
        ((__half2*)hi)[i * 2 + 0] = __halves2half2(h0, h1);
        ((__half2*)hi)[i * 2 + 1] = __halves2half2(h2, h3);
        ((__half2*)lo)[i * 2 + 0] = __halves2half2(
            __float2half(v.x - __half2float(h0)), __float2half(v.y - __half2float(h1)));
        ((__half2*)lo)[i * 2 + 1] = __halves2half2(
            __float2half(v.z - __half2float(h2)), __float2half(v.w - __half2float(h3)));
    }
}
__global__ void bias2(const float* a, const float* b, const float* c,
                      const float* d, float* o0, float* o1) {
    int i = blockIdx.x * 256 + threadIdx.x;
    if (i < kH) { o0[i] = a[i] + b[i]; o1[i] = c[i] + d[i]; }
}
__global__ void zero_flags() {
    int i = blockIdx.x * 256 + threadIdx.x;
    if (i < kT * 8) {
        ((int*)g_pf0)[i] = 0; ((int*)g_pf1)[i] = 0;
        ((int*)g_hf0)[i] = 0; ((int*)g_hf1)[i] = 0;
    }
}

// ---------------------------------------------------------------------------
// Big fp16-x2 GEMM for X0: C = Ah @ (Whi+Wlo)^T + bias.  128x128 tiles.
// ---------------------------------------------------------------------------
#define GRS 144
#define GBUF (128 * GRS)
#define GEMM_SMEM (3 * GBUF)   // 55296

__global__ void __launch_bounds__(256) gemm_h(
    const __half* __restrict__ Ah, const __half* __restrict__ Whi,
    const __half* __restrict__ Wlo, const float* __restrict__ bias,
    float* __restrict__ C)
{
    extern __shared__ char sm[];
    char* pA  = sm;
    char* pWh = sm + GBUF;
    char* pWl = sm + 2 * GBUF;

    const int tid = threadIdx.x, lane = tid & 31, wid = tid >> 5;
    const int n0 = blockIdx.x * 128, m0 = blockIdx.y * 128;
    const int wm = (wid >> 1) * 32, wn = (wid & 1) * 64;

    const uint32_t aOff = smem_u32(pA) + (wm + (lane & 15)) * GRS + (lane >> 4) * 16;
    const int brow = wn + (lane & 7) + ((lane >> 4) & 1) * 8;
    const uint32_t bOffH = smem_u32(pWh) + brow * GRS + ((lane >> 3) & 1) * 16;
    const uint32_t bOffL = smem_u32(pWl) + brow * GRS + ((lane >> 3) & 1) * 16;

    float acc[2][8][4];
#pragma unroll
    for (int a = 0; a < 2; a++)
#pragma unroll
        for (int b = 0; b < 8; b++)
#pragma unroll
            for (int c = 0; c < 4; c++) acc[a][b][c] = 0.f;

    for (int k0 = 0; k0 < kH; k0 += 64) {
        __syncthreads();
#pragma unroll
        for (int i = 0; i < 4; i++) {
            int q = tid + i * 256;             // 0..1023 (128 rows x 8 uint4)
            int row = q >> 3, c16 = q & 7;
            *(uint4*)(pA  + row * GRS + c16 * 16) =
                *((const uint4*)(Ah  + (size_t)(m0 + row) * kH + k0) + c16);
            *(uint4*)(pWh + row * GRS + c16 * 16) =
                *((const uint4*)(Whi + (size_t)(n0 + row) * kH + k0) + c16);
            *(uint4*)(pWl + row * GRS + c16 * 16) =
                *((const uint4*)(Wlo + (size_t)(n0 + row) * kH + k0) + c16);
        }
        __syncthreads();
#pragma unroll
        for (int kk = 0; kk < 4; kk++) {
            uint32_t ah0[4], ah1[4];
            LDSM4(ah0, aOff + kk * 32);
            LDSM4(ah1, aOff + 16 * GRS + kk * 32);
#pragma unroll
            for (int np = 0; np < 4; np++) {
                uint32_t bh[4], bl[4];
                LDSM4(bh, bOffH + np * 16 * GRS + kk * 32);
                LDSM4(bl, bOffL + np * 16 * GRS + kk * 32);
                HMMA(acc[0][np*2+0], ah0, bh+0); HMMA(acc[0][np*2+1], ah0, bh+2);
                HMMA(acc[1][np*2+0], ah1, bh+0); HMMA(acc[1][np*2+1], ah1, bh+2);
                HMMA(acc[0][np*2+0], ah0, bl+0); HMMA(acc[0][np*2+1], ah0, bl+2);
                HMMA(acc[1][np*2+0], ah1, bl+0); HMMA(acc[1][np*2+1], ah1, bl+2);
            }
        }
    }
    const int g = lane >> 2, tg2 = (lane & 3) * 2;
#pragma unroll
    for (int mf = 0; mf < 2; mf++)
#pragma unroll
        for (int nt = 0; nt < 8; nt++) {
            int m = m0 + wm + mf * 16 + g;
            int n = n0 + wn + nt * 8 + tg2;
            float b0 = bias[n], b1 = bias[n + 1];
            *(float2*)(C + (size_t)m * kH + n) =
                make_float2(acc[mf][nt][0] + b0, acc[mf][nt][1] + b1);
            *(float2*)(C + (size_t)(m + 8) * kH + n) =
                make_float2(acc[mf][nt][2] + b0, acc[mf][nt][3] + b1);
        }
}

// ---------------------------------------------------------------------------
// Warp-specialized fused recurrence, fp16 x2, 512 threads.
// 128 CTAs = 8 mt(128 cols) x 16 kc(64 k). Warps 0-7: layer0; 8-15: layer1.
// Warp tile: 16 batch rows x 64 cols (bg = gw&3, ch = gw>>2).
// ---------------------------------------------------------------------------
#define RS2 144
#define SL  (128 * RS2)               // 18432
#define HBf (64 * RS2)                // 9216
#define OHA  (6 * SL)
#define OHB0 (6 * SL + HBf)
#define OHB1 (6 * SL + 2 * HBf)
#define RNN_SMEM (6 * SL + 3 * HBf)   // 138240

__device__ __forceinline__ void stage_h16(char* dst, const __half* __restrict__ src,
                                          int k0, int gtid)
{
#pragma unroll
    for (int i = 0; i < 2; i++) {
        int q = gtid + i * 256;                // 0..511 (64 rows x 8 uint4)
        int row = q >> 3, c16 = q & 7;
        uint4 v = __ldcg((const uint4*)(src + (size_t)row * kH + k0) + c16);
        *(uint4*)(dst + row * RS2 + c16 * 16) = v;
    }
}

__global__ void __launch_bounds__(512) rnn_ws(
    float* __restrict__ out_y, float* __restrict__ hfin0,
    float* __restrict__ hfin1)
{
    extern __shared__ char sm[];
    const int tid = threadIdx.x, lane = tid & 31, wid = tid >> 5;
    const int cta = blockIdx.x;
    const int mt = cta >> 4;                  // 0..7 (128 hidden cols)
    const int kc = cta & 15;                  // 0..15 (64-k chunk)
    const int h0c = mt * 128;
    const int k0 = kc * 64;
    const int ktile = kc >> 1;
    const int group = wid >> 3;               // 0 = layer0, 1 = layer1
    const int gw = wid & 7;
    const int gtid = tid & 255;

    // ---- cooperative staging of 6 step-invariant W slices ----
    {
        const __half* wsrc[6] = { g_s.Whi[1], g_s.Wlo[1], g_s.Whi[2],
                                  g_s.Wlo[2], g_s.Whi[3], g_s.Wlo[3] };
#pragma unroll
        for (int sl = 0; sl < 6; sl++) {
            char* dst = sm + sl * SL;
            const __half* src = wsrc[sl];
#pragma unroll
            for (int i = 0; i < 2; i++) {
                int q = tid + i * 512;          // 0..1023 (128 rows x 8 uint4)
                int row = q >> 3, c16 = q & 7;
                *(uint4*)(dst + row * RS2 + c16 * 16) =
                    *((const uint4*)(src + (size_t)(h0c + row) * kH + k0) + c16);
            }
        }
    }
    __syncthreads();    // LAST full-CTA sync; groups diverge permanently below

    const int bg = gw & 3, ch = gw >> 2;
    const int bb = bg * 16;                            // warp's 16 batch rows
    const uint32_t arow = (bb + (lane & 15)) * RS2 + (lane >> 4) * 16;
    const int brow = ch * 64 + (lane & 7) + ((lane >> 4) & 1) * 8;
    const uint32_t bsel = ((lane >> 3) & 1) * 16;

    const uint32_t bW0H = smem_u32(sm + 0 * SL) + brow * RS2 + bsel;
    const uint32_t bW0L = smem_u32(sm + 1 * SL) + brow * RS2 + bsel;
    const uint32_t bW1H = smem_u32(sm + 2 * SL) + brow * RS2 + bsel;
    const uint32_t bW1L = smem_u32(sm + 3 * SL) + brow * RS2 + bsel;
    const uint32_t bW2H = smem_u32(sm + 4 * SL) + brow * RS2 + bsel;
    const uint32_t bW2L = smem_u32(sm + 5 * SL) + brow * RS2 + bsel;

    const int g = lane >> 2, tg2 = (lane & 3) * 2;

    // reduce/publish ownership: 256 threads cover 64 rows x 8 cols (2 each)
    const int rb   = gtid >> 2;                        // batch row 0..63
    const int rcol = kc * 8 + (gtid & 3) * 2;          // col within 128-tile
    const int gcol = h0c + rcol;
    const int gidx = rb * kH + gcol;

    if (group == 0) {
        // ================= GROUP A: layer-0 serial chain =================
        char* pHA = sm + OHA;
        const uint32_t aH = smem_u32(pHA) + arow;

        for (int t = 0; t < kT; t++) {
            if (gtid == 0) {
                if (t >= 1) spin_ge(&g_hf0[t - 1][ktile], 16);
                if (t >= 4) spin_ge(&g_hf0[t - 4][mt], 16);   // p0 slot guard
            }
            BARA();
            stage_h16(pHA, t ? g_h0 + (size_t)(t - 1) * kBH : g_s.hin, k0, gtid);
            float2 xv = __ldcg((const float2*)(g_s.X + (size_t)t * kBH + gidx));
            BARA();

            float acc[8][4];
#pragma unroll
            for (int a = 0; a < 8; a++)
#pragma unroll
                for (int c = 0; c < 4; c++) acc[a][c] = 0.f;
#pragma unroll
            for (int kk = 0; kk < 4; kk++) {
                uint32_t ah[4];
                LDSM4(ah, aH + kk * 32);
#pragma unroll
                for (int np = 0; np < 4; np++) {
                    uint32_t wh[4], wl[4];
                    LDSM4(wh, bW0H + np * 16 * RS2 + kk * 32);
                    LDSM4(wl, bW0L + np * 16 * RS2 + kk * 32);
                    HMMA(acc[np*2+0], ah, wh+0); HMMA(acc[np*2+1], ah, wh+2);
                    HMMA(acc[np*2+0], ah, wl+0); HMMA(acc[np*2+1], ah, wl+2);
                }
            }

            float* pp = &g_p0[t & 3][mt][kc][0];
            const int b = bb + g;
#pragma unroll
            for (int nt = 0; nt < 8; nt++) {
                int col = ch * 64 + nt * 8 + tg2;
                *(float2*)(pp + b * 128 + col) = make_float2(acc[nt][0], acc[nt][1]);
                *(float2*)(pp + (b + 8) * 128 + col) = make_float2(acc[nt][2], acc[nt][3]);
            }
            BARA();
            if (gtid == 0) {
                __threadfence(); atomicAdd(&g_pf0[t][mt], 1);
                spin_ge(&g_pf0[t][mt], 16);
            }
            BARA();

            float2 s = xv;
            const float* base = &g_p0[t & 3][mt][0][0];
#pragma unroll
            for (int rr = 0; rr < 16; rr++) {
                float2 p = __ldcg((const float2*)(base + rr * 8192 + rb * 128 + rcol));
                s.x += p.x; s.y += p.y;
            }
            float hx = tanhf(s.x), hy = tanhf(s.y);
            *(__half2*)(g_h0 + (size_t)t * kBH + gidx) = __floats2half2_rn(hx, hy);
            if (t == kT - 1) *(float2*)(hfin0 + gidx) = make_float2(hx, hy);
            BARA();
            if (gtid == 0) { __threadfence(); atomicAdd(&g_hf0[t][mt], 1); }
        }
    } else {
        // ================= GROUP B: layer-1 trailing chain =================
        char* pB0 = sm + OHB0;
        char* pB1 = sm + OHB1;
        const uint32_t a0 = smem_u32(pB0) + arow;
        const uint32_t a1 = smem_u32(pB1) + arow;
        const float2 bv = *(const float2*)(g_s.bias[1] + gcol);

        for (int t = 0; t < kT; t++) {
            if (gtid == 0) {
                spin_ge(&g_hf0[t][ktile], 16);                 // h0[t]
                if (t >= 1) spin_ge(&g_hf1[t - 1][ktile], 16); // h1[t-1]
                if (t >= 4) spin_ge(&g_hf1[t - 4][mt], 16);    // p1 slot guard
            }
            BARB();
            stage_h16(pB0, g_h0 + (size_t)t * kBH, k0, gtid);
            stage_h16(pB1, t ? g_h1 + (size_t)(t - 1) * kBH : g_s.hin + kBH,
                      k0, gtid);
            BARB();

            float acc[8][4];
#pragma unroll
            for (int a = 0; a < 8; a++)
#pragma unroll
                for (int c = 0; c < 4; c++) acc[a][c] = 0.f;
#pragma unroll
            for (int kk = 0; kk < 4; kk++) {
                uint32_t x0[4], x1[4];
                LDSM4(x0, a0 + kk * 32);
                LDSM4(x1, a1 + kk * 32);
#pragma unroll
                for (int np = 0; np < 4; np++) {
                    uint32_t w1h[4], w1l[4], w2h[4], w2l[4];
                    LDSM4(w1h, bW1H + np * 16 * RS2 + kk * 32);
                    LDSM4(w1l, bW1L + np * 16 * RS2 + kk * 32);
                    LDSM4(w2h, bW2H + np * 16 * RS2 + kk * 32);
                    LDSM4(w2l, bW2L + np * 16 * RS2 + kk * 32);
                    HMMA(acc[np*2+0], x0, w1h+0); HMMA(acc[np*2+1], x0, w1h+2);
                    HMMA(acc[np*2+0], x1, w2h+0); HMMA(acc[np*2+1], x1, w2h+2);
                    HMMA(acc[np*2+0], x0, w1l+0); HMMA(acc[np*2+1], x0, w1l+2);
                    HMMA(acc[np*2+0], x1, w2l+0); HMMA(acc[np*2+1], x1, w2l+2);
                }
            }

            float* pp = &g_p1[t & 3][mt][kc][0];
            const int b = bb + g;
#pragma unroll
            for (int nt = 0; nt < 8; nt++) {
                int col = ch * 64 + nt * 8 + tg2;
                *(float2*)(pp + b * 128 + col) = make_float2(acc[nt][0], acc[nt][1]);
                *(float2*)(pp + (b + 8) * 128 + col) = make_float2(acc[nt][2], acc[nt][3]);
            }
            BARB();
            if (gtid == 0) {
                __threadfence(); atomicAdd(&g_pf1[t][mt], 1);
                spin_ge(&g_pf1[t][mt], 16);
            }
            BARB();

            float2 s = bv;
            const float* base = &g_p1[t & 3][mt][0][0];
#pragma unroll
            for (int rr = 0; rr < 16; rr++) {
                float2 p = __ldcg((const float2*)(base + rr * 8192 + rb * 128 + rcol));
                s.x += p.x; s.y += p.y;
            }
            float hx = tanhf(s.x), hy = tanhf(s.y);
            *(float2*)(out_y + (size_t)t * kBH + gidx) = make_float2(hx, hy);
            *(__half2*)(g_h1 + (size_t)t * kBH + gidx) = __floats2half2_rn(hx, hy);
            if (t == kT - 1) *(float2*)(hfin1 + gidx) = make_float2(hx, hy);
            BARB();
            if (gtid == 0) { __threadfence(); atomicAdd(&g_hf1[t][mt], 1); }
        }
    }
}

// ---------------------------------------------------------------------------
// Launch
// ---------------------------------------------------------------------------
extern "C" void kernel_launch(void* const* d_in, const int* in_sizes, int n_in,
                              void* d_out, int out_size)
{
    const float* input = (const float*)d_in[0];
    const float* h_0   = (const float*)d_in[1];
    const float* W_ih0 = (const float*)d_in[2];
    const float* b_ih0 = (const float*)d_in[3];
    const float* W_hh0 = (const float*)d_in[4];
    const float* b_hh0 = (const float*)d_in[5];
    const float* W_ih1 = (const float*)d_in[6];
    const float* b_ih1 = (const float*)d_in[7];
    const float* W_hh1 = (const float*)d_in[8];
    const float* b_hh1 = (const float*)d_in[9];
    float* out = (float*)d_out;

    Scratch* s = nullptr;
    cudaGetSymbolAddress((void**)&s, g_s);

    cudaFuncSetAttribute(gemm_h, cudaFuncAttributeMaxDynamicSharedMemorySize, GEMM_SMEM);
    cudaFuncSetAttribute(rnn_ws, cudaFuncAttributeMaxDynamicSharedMemorySize, RNN_SMEM);

    zero_flags<<<16, 256>>>();
    cvt_half<<<2048, 256>>>(input, s->Ah, kTBH / 4);
    split_half<<<1024, 256>>>(W_ih0, s->Whi[0], s->Wlo[0], kH * kH / 4);
    split_half<<<1024, 256>>>(W_hh0, s->Whi[1], s->Wlo[1], kH * kH / 4);
    split_half<<<1024, 256>>>(W_ih1, s->Whi[2], s->Wlo[2], kH * kH / 4);
    split_half<<<1024, 256>>>(W_hh1, s->Whi[3], s->Wlo[3], kH * kH / 4);
    cvt_half<<<128, 256>>>(h_0, s->hin, 2 * kBH / 4);
    bias2<<<4, 256>>>(b_ih0, b_hh0, b_ih1, b_hh1, s->bias[0], s->bias[1]);

    dim3 ggrid(kH / 128, kTB / 128);
    gemm_h<<<ggrid, 256, GEMM_SMEM>>>(s->Ah, s->Whi[0], s->Wlo[0],
                                      s->bias[0], s->X);

    rnn_ws<<<128, 512, RNN_SMEM>>>(out, out + (size_t)kTBH,
                                   out + (size_t)kTBH + kBH);
}

// round 15
// speedup vs baseline: 1.5126x; 1.0856x over previous
#include <cuda_runtime.h>
#include <cuda_fp16.h>
#include <math.h>
#include <stdint.h>

#define kT   512
#define kB   64
#define kH   1024
#define kBH  65536
#define kTB  32768
#define kTBH 33554432

// ---------------------------------------------------------------------------
// Scratch (device globals; allocations forbidden)
// ---------------------------------------------------------------------------
struct __align__(16) Scratch {
    float  X[kTBH];                      // X0 = input @ W_ih0^T + biases (fp32)
    __half Ah[kTBH];                     // input as fp16
    __half Whi[4][kH * kH];              // W hi: ih0, hh0, ih1, hh1
    __half Wlo[4][kH * kH];              // W lo (fp16 residual)
    float  bias[2][kH];
    __half hin[2 * kBH];                 // initial h (fp16)
};
__device__ Scratch g_s;

// write-once hidden histories (fp16)
__device__ __half g_h0[kTBH], g_h1[kTBH];

// k-split partials, 4-deep slots: [slot][mt(16)][kc(8)][64*64]
__device__ float g_p0[4][16][8][64 * 64];
__device__ float g_p1[4][16][8][64 * 64];

// dataflow flags (monotonic counters; fan-in 8; 16 tiles)
__device__ int g_pf0[kT][16], g_pf1[kT][16];
__device__ int g_hf0[kT][16], g_hf1[kT][16];

// ---------------------------------------------------------------------------
// Warp MMA primitives (baseline ISA: fp16 HMMA + ldmatrix)
// ---------------------------------------------------------------------------
__device__ __forceinline__ uint32_t smem_u32(const void* p) {
    uint32_t r;
    asm("{ .reg .u64 t; cvta.to.shared.u64 t, %1; cvt.u32.u64 %0, t; }" : "=r"(r) : "l"(p));
    return r;
}
#define LDSM4(r, addr)                                                        \
    asm volatile("ldmatrix.sync.aligned.m8n8.x4.shared.b16 {%0,%1,%2,%3}, [%4];" \
        : "=r"((r)[0]), "=r"((r)[1]), "=r"((r)[2]), "=r"((r)[3]) : "r"(addr))
#define HMMA(d, a, b)                                                         \
    asm volatile("mma.sync.aligned.m16n8k16.row.col.f32.f16.f16.f32 "         \
        "{%0,%1,%2,%3}, {%4,%5,%6,%7}, {%8,%9}, {%0,%1,%2,%3};"               \
        : "+f"((d)[0]), "+f"((d)[1]), "+f"((d)[2]), "+f"((d)[3])              \
        : "r"((a)[0]), "r"((a)[1]), "r"((a)[2]), "r"((a)[3]),                 \
          "r"((b)[0]), "r"((b)[1]))

#define BARA() asm volatile("bar.sync 1, 256;" ::: "memory")
#define BARB() asm volatile("bar.sync 2, 256;" ::: "memory")

__device__ __forceinline__ void spin_ge(const int* f, int n) {
    while (true) {
        int v;
        asm volatile("ld.acquire.gpu.global.s32 %0, [%1];" : "=r"(v) : "l"(f));
        if (v >= n) break;
        __nanosleep(20);
    }
}

// ---------------------------------------------------------------------------
// prep kernels
// ---------------------------------------------------------------------------
__global__ void cvt_half(const float* __restrict__ s, __half* __restrict__ d, int n4) {
    int stride = gridDim.x * blockDim.x;
    for (int i = blockIdx.x * blockDim.x + threadIdx.x; i < n4; i += stride) {
        float4 v = ((const float4*)s)[i];
        __half2* o = (__half2*)d + i * 2;
        o[0] = __floats2half2_rn(v.x, v.y);
        o[1] = __floats2half2_rn(v.z, v.w);
    }
}
__global__ void split_half(const float* __restrict__ s, __half* __restrict__ hi,
                           __half* __restrict__ lo, int n4) {
    int stride = gridDim.x * blockDim.x;
    for (int i = blockIdx.x * blockDim.x + threadIdx.x; i < n4; i += stride) {
        float4 v = ((const float4*)s)[i];
        __half h0 = __float2half(v.x), h1 = __float2half(v.y);
        __half h2 = __float2half(v.z), h3 = __float2half(v.w);
        ((__half2*)hi)[i * 2 + 0] = __halves2half2(h0, h1);
        ((__half2*)hi)[i * 2 + 1] = __halves2half2(h2, h3);
        ((__half2*)lo)[i * 2 + 0] = __halves2half2(
            __float2half(v.x - __half2float(h0)), __float2half(v.y - __half2float(h1)));
        ((__half2*)lo)[i * 2 + 1] = __halves2half2(
            __float2half(v.z - __half2float(h2)), __float2half(v.w - __half2float(h3)));
    }
}
__global__ void bias2(const float* a, const float* b, const float* c,
                      const float* d, float* o0, float* o1) {
    int i = blockIdx.x * 256 + threadIdx.x;
    if (i < kH) { o0[i] = a[i] + b[i]; o1[i] = c[i] + d[i]; }
}
__global__ void zero_flags() {
    int i = blockIdx.x * 256 + threadIdx.x;
    if (i < kT * 16) {
        ((int*)g_pf0)[i] = 0; ((int*)g_pf1)[i] = 0;
        ((int*)g_hf0)[i] = 0; ((int*)g_hf1)[i] = 0;
    }
}

// ---------------------------------------------------------------------------
// Big fp16-x2 GEMM for X0 (proven R14 kernel, unchanged)
// ---------------------------------------------------------------------------
#define GRS 144
#define GBUF (128 * GRS)
#define GEMM_SMEM (3 * GBUF)   // 55296

__global__ void __launch_bounds__(256) gemm_h(
    const __half* __restrict__ Ah, const __half* __restrict__ Whi,
    const __half* __restrict__ Wlo, const float* __restrict__ bias,
    float* __restrict__ C)
{
    extern __shared__ char sm[];
    char* pA  = sm;
    char* pWh = sm + GBUF;
    char* pWl = sm + 2 * GBUF;

    const int tid = threadIdx.x, lane = tid & 31, wid = tid >> 5;
    const int n0 = blockIdx.x * 128, m0 = blockIdx.y * 128;
    const int wm = (wid >> 1) * 32, wn = (wid & 1) * 64;

    const uint32_t aOff = smem_u32(pA) + (wm + (lane & 15)) * GRS + (lane >> 4) * 16;
    const int brow = wn + (lane & 7) + ((lane >> 4) & 1) * 8;
    const uint32_t bOffH = smem_u32(pWh) + brow * GRS + ((lane >> 3) & 1) * 16;
    const uint32_t bOffL = smem_u32(pWl) + brow * GRS + ((lane >> 3) & 1) * 16;

    float acc[2][8][4];
#pragma unroll
    for (int a = 0; a < 2; a++)
#pragma unroll
        for (int b = 0; b < 8; b++)
#pragma unroll
            for (int c = 0; c < 4; c++) acc[a][b][c] = 0.f;

    for (int k0 = 0; k0 < kH; k0 += 64) {
        __syncthreads();
#pragma unroll
        for (int i = 0; i < 4; i++) {
            int q = tid + i * 256;
            int row = q >> 3, c16 = q & 7;
            *(uint4*)(pA  + row * GRS + c16 * 16) =
                *((const uint4*)(Ah  + (size_t)(m0 + row) * kH + k0) + c16);
            *(uint4*)(pWh + row * GRS + c16 * 16) =
                *((const uint4*)(Whi + (size_t)(n0 + row) * kH + k0) + c16);
            *(uint4*)(pWl + row * GRS + c16 * 16) =
                *((const uint4*)(Wlo + (size_t)(n0 + row) * kH + k0) + c16);
        }
        __syncthreads();
#pragma unroll
        for (int kk = 0; kk < 4; kk++) {
            uint32_t ah0[4], ah1[4];
            LDSM4(ah0, aOff + kk * 32);
            LDSM4(ah1, aOff + 16 * GRS + kk * 32);
#pragma unroll
            for (int np = 0; np < 4; np++) {
                uint32_t bh[4], bl[4];
                LDSM4(bh, bOffH + np * 16 * GRS + kk * 32);
                LDSM4(bl, bOffL + np * 16 * GRS + kk * 32);
                HMMA(acc[0][np*2+0], ah0, bh+0); HMMA(acc[0][np*2+1], ah0, bh+2);
                HMMA(acc[1][np*2+0], ah1, bh+0); HMMA(acc[1][np*2+1], ah1, bh+2);
                HMMA(acc[0][np*2+0], ah0, bl+0); HMMA(acc[0][np*2+1], ah0, bl+2);
                HMMA(acc[1][np*2+0], ah1, bl+0); HMMA(acc[1][np*2+1], ah1, bl+2);
            }
        }
    }
    const int g = lane >> 2, tg2 = (lane & 3) * 2;
#pragma unroll
    for (int mf = 0; mf < 2; mf++)
#pragma unroll
        for (int nt = 0; nt < 8; nt++) {
            int m = m0 + wm + mf * 16 + g;
            int n = n0 + wn + nt * 8 + tg2;
            float b0 = bias[n], b1 = bias[n + 1];
            *(float2*)(C + (size_t)m * kH + n) =
                make_float2(acc[mf][nt][0] + b0, acc[mf][nt][1] + b1);
            *(float2*)(C + (size_t)(m + 8) * kH + n) =
                make_float2(acc[mf][nt][2] + b0, acc[mf][nt][3] + b1);
        }
}

// ---------------------------------------------------------------------------
// Warp-specialized fused recurrence, fp16 x2, 512 threads.
// 128 CTAs = 16 mt(64 cols) x 8 kc(128 k).   <- fan-in 8, half partial traffic
// Warps 0-7: layer0 (group A).  Warps 8-15: layer1 (group B).
// Warp tile: 16 batch rows (bg) x 32 cols (cg).
// ---------------------------------------------------------------------------
#define RS2 272                       // 128 fp16 + 8 pad
#define SLW (64 * RS2)                // 17408: one W slice [64 rows][128 k]
#define OHA  (6 * SLW)                // h buffers follow the 6 W slices
#define OHB0 (7 * SLW)
#define OHB1 (8 * SLW)
#define RNN_SMEM (9 * SLW)            // 156672

__device__ __forceinline__ void stage_h16(char* dst, const __half* __restrict__ src,
                                          int k0, int gtid)
{
#pragma unroll
    for (int i = 0; i < 4; i++) {
        int q = gtid + i * 256;                // 0..1023 (64 rows x 16 uint4)
        int row = q >> 4, c16 = q & 15;
        uint4 v = __ldcg((const uint4*)(src + (size_t)row * kH + k0) + c16);
        *(uint4*)(dst + row * RS2 + c16 * 16) = v;
    }
}

__global__ void __launch_bounds__(512) rnn_ws(
    float* __restrict__ out_y, float* __restrict__ hfin0,
    float* __restrict__ hfin1)
{
    extern __shared__ char sm[];
    const int tid = threadIdx.x, lane = tid & 31, wid = tid >> 5;
    const int cta = blockIdx.x;
    const int mt = cta >> 3;                  // 0..15 (64 hidden cols)
    const int kc = cta & 7;                   // 0..7 (128-k chunk)
    const int h0c = mt * 64;
    const int k0 = kc * 128;
    const int kt0 = 2 * kc, kt1 = 2 * kc + 1; // h-tiles covering our k range
    const int group = wid >> 3;               // 0 = layer0, 1 = layer1
    const int gw = wid & 7;
    const int gtid = tid & 255;

    // ---- cooperative staging of 6 step-invariant W slices [64 rows][128 k] ----
    {
        const __half* wsrc[6] = { g_s.Whi[1], g_s.Wlo[1], g_s.Whi[2],
                                  g_s.Wlo[2], g_s.Whi[3], g_s.Wlo[3] };
#pragma unroll
        for (int sl = 0; sl < 6; sl++) {
            char* dst = sm + sl * SLW;
            const __half* src = wsrc[sl];
#pragma unroll
            for (int i = 0; i < 2; i++) {
                int q = tid + i * 512;          // 0..1023 (64 rows x 16 uint4)
                int row = q >> 4, c16 = q & 15;
                *(uint4*)(dst + row * RS2 + c16 * 16) =
                    *((const uint4*)(src + (size_t)(h0c + row) * kH + k0) + c16);
            }
        }
    }
    __syncthreads();    // LAST full-CTA sync; groups diverge permanently below

    const int bg = gw & 3, cg = gw >> 2;               // 16 b-rows x 32 cols
    const int bb = bg * 16;
    const uint32_t arow = (bb + (lane & 15)) * RS2 + (lane >> 4) * 16;
    const int brow = cg * 32 + (lane & 7) + ((lane >> 4) & 1) * 8;
    const uint32_t bsel = ((lane >> 3) & 1) * 16;

    const uint32_t bW0H = smem_u32(sm + 0 * SLW) + brow * RS2 + bsel;
    const uint32_t bW0L = smem_u32(sm + 1 * SLW) + brow * RS2 + bsel;
    const uint32_t bW1H = smem_u32(sm + 2 * SLW) + brow * RS2 + bsel;
    const uint32_t bW1L = smem_u32(sm + 3 * SLW) + brow * RS2 + bsel;
    const uint32_t bW2H = smem_u32(sm + 4 * SLW) + brow * RS2 + bsel;
    const uint32_t bW2L = smem_u32(sm + 5 * SLW) + brow * RS2 + bsel;

    const int g = lane >> 2, tg2 = (lane & 3) * 2;

    // reduce/publish ownership: 256 threads cover 64 rows x 8 cols (2 each)
    const int rb   = gtid >> 2;                        // batch row 0..63
    const int rcol = kc * 8 + (gtid & 3) * 2;          // col within 64-tile
    const int gcol = h0c + rcol;
    const int gidx = rb * kH + gcol;

    if (group == 0) {
        // ================= GROUP A: layer-0 serial chain =================
        char* pHA = sm + OHA;
        const uint32_t aH = smem_u32(pHA) + arow;

        for (int t = 0; t < kT; t++) {
            if (gtid == 0) {
                if (t >= 1) { spin_ge(&g_hf0[t - 1][kt0], 8);
                              spin_ge(&g_hf0[t - 1][kt1], 8); }
                if (t >= 4) spin_ge(&g_hf0[t - 4][mt], 8);    // p0 slot guard
            }
            BARA();
            stage_h16(pHA, t ? g_h0 + (size_t)(t - 1) * kBH : g_s.hin, k0, gtid);
            float2 xv = __ldcg((const float2*)(g_s.X + (size_t)t * kBH + gidx));
            BARA();

            float acc[4][4];
#pragma unroll
            for (int a = 0; a < 4; a++)
#pragma unroll
                for (int c = 0; c < 4; c++) acc[a][c] = 0.f;
#pragma unroll
            for (int kk = 0; kk < 8; kk++) {
                uint32_t ah[4];
                LDSM4(ah, aH + kk * 32);
#pragma unroll
                for (int np = 0; np < 2; np++) {
                    uint32_t wh[4], wl[4];
                    LDSM4(wh, bW0H + np * 16 * RS2 + kk * 32);
                    LDSM4(wl, bW0L + np * 16 * RS2 + kk * 32);
                    HMMA(acc[np*2+0], ah, wh+0); HMMA(acc[np*2+1], ah, wh+2);
                    HMMA(acc[np*2+0], ah, wl+0); HMMA(acc[np*2+1], ah, wl+2);
                }
            }

            float* pp = &g_p0[t & 3][mt][kc][0];
            const int b = bb + g;
#pragma unroll
            for (int nt = 0; nt < 4; nt++) {
                int col = cg * 32 + nt * 8 + tg2;
                *(float2*)(pp + b * 64 + col) = make_float2(acc[nt][0], acc[nt][1]);
                *(float2*)(pp + (b + 8) * 64 + col) = make_float2(acc[nt][2], acc[nt][3]);
            }
            BARA();
            if (gtid == 0) {
                __threadfence(); atomicAdd(&g_pf0[t][mt], 1);
                spin_ge(&g_pf0[t][mt], 8);
            }
            BARA();

            float2 s = xv;
            const float* base = &g_p0[t & 3][mt][0][0];
#pragma unroll
            for (int rr = 0; rr < 8; rr++) {
                float2 p = __ldcg((const float2*)(base + rr * 4096 + rb * 64 + rcol));
                s.x += p.x; s.y += p.y;
            }
            float hx = tanhf(s.x), hy = tanhf(s.y);
            *(__half2*)(g_h0 + (size_t)t * kBH + gidx) = __floats2half2_rn(hx, hy);
            if (t == kT - 1) *(float2*)(hfin0 + gidx) = make_float2(hx, hy);
            BARA();
            if (gtid == 0) { __threadfence(); atomicAdd(&g_hf0[t][mt], 1); }
        }
    } else {
        // ================= GROUP B: layer-1 trailing chain =================
        char* pB0 = sm + OHB0;
        char* pB1 = sm + OHB1;
        const uint32_t a0 = smem_u32(pB0) + arow;
        const uint32_t a1 = smem_u32(pB1) + arow;
        const float2 bv = *(const float2*)(g_s.bias[1] + gcol);

        for (int t = 0; t < kT; t++) {
            if (gtid == 0) {
                spin_ge(&g_hf0[t][kt0], 8);
                spin_ge(&g_hf0[t][kt1], 8);
                if (t >= 1) { spin_ge(&g_hf1[t - 1][kt0], 8);
                              spin_ge(&g_hf1[t - 1][kt1], 8); }
                if (t >= 4) spin_ge(&g_hf1[t - 4][mt], 8);    // p1 slot guard
            }
            BARB();
            stage_h16(pB0, g_h0 + (size_t)t * kBH, k0, gtid);
            stage_h16(pB1, t ? g_h1 + (size_t)(t - 1) * kBH : g_s.hin + kBH,
                      k0, gtid);
            BARB();

            float acc[4][4];
#pragma unroll
            for (int a = 0; a < 4; a++)
#pragma unroll
                for (int c = 0; c < 4; c++) acc[a][c] = 0.f;
#pragma unroll
            for (int kk = 0; kk < 8; kk++) {
                uint32_t x0[4], x1[4];
                LDSM4(x0, a0 + kk * 32);
                LDSM4(x1, a1 + kk * 32);
#pragma unroll
                for (int np = 0; np < 2; np++) {
                    uint32_t w1h[4], w1l[4], w2h[4], w2l[4];
                    LDSM4(w1h, bW1H + np * 16 * RS2 + kk * 32);
                    LDSM4(w1l, bW1L + np * 16 * RS2 + kk * 32);
                    LDSM4(w2h, bW2H + np * 16 * RS2 + kk * 32);
                    LDSM4(w2l, bW2L + np * 16 * RS2 + kk * 32);
                    HMMA(acc[np*2+0], x0, w1h+0); HMMA(acc[np*2+1], x0, w1h+2);
                    HMMA(acc[np*2+0], x1, w2h+0); HMMA(acc[np*2+1], x1, w2h+2);
                    HMMA(acc[np*2+0], x0, w1l+0); HMMA(acc[np*2+1], x0, w1l+2);
                    HMMA(acc[np*2+0], x1, w2l+0); HMMA(acc[np*2+1], x1, w2l+2);
                }
            }

            float* pp = &g_p1[t & 3][mt][kc][0];
            const int b = bb + g;
#pragma unroll
            for (int nt = 0; nt < 4; nt++) {
                int col = cg * 32 + nt * 8 + tg2;
                *(float2*)(pp + b * 64 + col) = make_float2(acc[nt][0], acc[nt][1]);
                *(float2*)(pp + (b + 8) * 64 + col) = make_float2(acc[nt][2], acc[nt][3]);
            }
            BARB();
            if (gtid == 0) {
                __threadfence(); atomicAdd(&g_pf1[t][mt], 1);
                spin_ge(&g_pf1[t][mt], 8);
            }
            BARB();

            float2 s = bv;
            const float* base = &g_p1[t & 3][mt][0][0];
#pragma unroll
            for (int rr = 0; rr < 8; rr++) {
                float2 p = __ldcg((const float2*)(base + rr * 4096 + rb * 64 + rcol));
                s.x += p.x; s.y += p.y;
            }
            float hx = tanhf(s.x), hy = tanhf(s.y);
            *(float2*)(out_y + (size_t)t * kBH + gidx) = make_float2(hx, hy);
            *(__half2*)(g_h1 + (size_t)t * kBH + gidx) = __floats2half2_rn(hx, hy);
            if (t == kT - 1) *(float2*)(hfin1 + gidx) = make_float2(hx, hy);
            BARB();
            if (gtid == 0) { __threadfence(); atomicAdd(&g_hf1[t][mt], 1); }
        }
    }
}

// ---------------------------------------------------------------------------
// Launch
// ---------------------------------------------------------------------------
extern "C" void kernel_launch(void* const* d_in, const int* in_sizes, int n_in,
                              void* d_out, int out_size)
{
    const float* input = (const float*)d_in[0];
    const float* h_0   = (const float*)d_in[1];
    const float* W_ih0 = (const float*)d_in[2];
    const float* b_ih0 = (const float*)d_in[3];
    const float* W_hh0 = (const float*)d_in[4];
    const float* b_hh0 = (const float*)d_in[5];
    const float* W_ih1 = (const float*)d_in[6];
    const float* b_ih1 = (const float*)d_in[7];
    const float* W_hh1 = (const float*)d_in[8];
    const float* b_hh1 = (const float*)d_in[9];
    float* out = (float*)d_out;

    Scratch* s = nullptr;
    cudaGetSymbolAddress((void**)&s, g_s);

    cudaFuncSetAttribute(gemm_h, cudaFuncAttributeMaxDynamicSharedMemorySize, GEMM_SMEM);
    cudaFuncSetAttribute(rnn_ws, cudaFuncAttributeMaxDynamicSharedMemorySize, RNN_SMEM);

    zero_flags<<<32, 256>>>();
    cvt_half<<<2048, 256>>>(input, s->Ah, kTBH / 4);
    split_half<<<1024, 256>>>(W_ih0, s->Whi[0], s->Wlo[0], kH * kH / 4);
    split_half<<<1024, 256>>>(W_hh0, s->Whi[1], s->Wlo[1], kH * kH / 4);
    split_half<<<1024, 256>>>(W_ih1, s->Whi[2], s->Wlo[2], kH * kH / 4);
    split_half<<<1024, 256>>>(W_hh1, s->Whi[3], s->Wlo[3], kH * kH / 4);
    cvt_half<<<128, 256>>>(h_0, s->hin, 2 * kBH / 4);
    bias2<<<4, 256>>>(b_ih0, b_hh0, b_ih1, b_hh1, s->bias[0], s->bias[1]);

    dim3 ggrid(kH / 128, kTB / 128);
    gemm_h<<<ggrid, 256, GEMM_SMEM>>>(s->Ah, s->Whi[0], s->Wlo[0],
                                      s->bias[0], s->X);

    rnn_ws<<<128, 512, RNN_SMEM>>>(out, out + (size_t)kTBH,
                                   out + (size_t)kTBH + kBH);
}

// round 16
// speedup vs baseline: 1.5493x; 1.0242x over previous
#include <cuda_runtime.h>
#include <cuda_fp16.h>
#include <math.h>
#include <stdint.h>

#define kT   512
#define kB   64
#define kH   1024
#define kBH  65536
#define kTB  32768
#define kTBH 33554432

// ---------------------------------------------------------------------------
// Scratch (device globals; allocations forbidden)
// ---------------------------------------------------------------------------
struct __align__(16) Scratch {
    float  X[kTBH];                      // X0 = input @ W_ih0^T + biases (fp32)
    __half Ah[kTBH];                     // input as fp16
    __half Whi[4][kH * kH];              // W hi: ih0, hh0, ih1, hh1
    __half Wlo[4][kH * kH];              // W lo (fp16 residual)
    float  bias[2][kH];
    __half hin[2 * kBH];                 // initial h (fp16)
};
__device__ Scratch g_s;

// write-once hidden histories (fp16)
__device__ __half g_h0[kTBH], g_h1[kTBH];

// k-split partials, 4-deep slots: [slot][mt(16)][kc(8)][64*64]
__device__ float g_p0[4][16][8][64 * 64];
__device__ float g_p1[4][16][8][64 * 64];

// dataflow flags (monotonic counters; fan-in 8; 16 tiles)
__device__ int g_pf0[kT][16], g_pf1[kT][16];
__device__ int g_hf0[kT][16], g_hf1[kT][16];

// ---------------------------------------------------------------------------
// Warp MMA primitives (baseline ISA: fp16 HMMA + ldmatrix)
// ---------------------------------------------------------------------------
__device__ __forceinline__ uint32_t smem_u32(const void* p) {
    uint32_t r;
    asm("{ .reg .u64 t; cvta.to.shared.u64 t, %1; cvt.u32.u64 %0, t; }" : "=r"(r) : "l"(p));
    return r;
}
#define LDSM4(r, addr)                                                        \
    asm volatile("ldmatrix.sync.aligned.m8n8.x4.shared.b16 {%0,%1,%2,%3}, [%4];" \
        : "=r"((r)[0]), "=r"((r)[1]), "=r"((r)[2]), "=r"((r)[3]) : "r"(addr))
#define HMMA(d, a, b)                                                         \
    asm volatile("mma.sync.aligned.m16n8k16.row.col.f32.f16.f16.f32 "         \
        "{%0,%1,%2,%3}, {%4,%5,%6,%7}, {%8,%9}, {%0,%1,%2,%3};"               \
        : "+f"((d)[0]), "+f"((d)[1]), "+f"((d)[2]), "+f"((d)[3])              \
        : "r"((a)[0]), "r"((a)[1]), "r"((a)[2]), "r"((a)[3]),                 \
          "r"((b)[0]), "r"((b)[1]))

#define BARA() asm volatile("bar.sync 1, 256;" ::: "memory")
#define BARB() asm volatile("bar.sync 2, 256;" ::: "memory")

// tight spin: detect latency = one L2 round trip
__device__ __forceinline__ void spin_ge(const int* f, int n) {
    while (true) {
        int v;
        asm volatile("ld.acquire.gpu.global.s32 %0, [%1];" : "=r"(v) : "l"(f));
        if (v >= n) break;
    }
}

// ---------------------------------------------------------------------------
// prep kernels
// ---------------------------------------------------------------------------
__global__ void cvt_half(const float* __restrict__ s, __half* __restrict__ d, int n4) {
    int stride = gridDim.x * blockDim.x;
    for (int i = blockIdx.x * blockDim.x + threadIdx.x; i < n4; i += stride) {
        float4 v = ((const float4*)s)[i];
        __half2* o = (__half2*)d + i * 2;
        o[0] = __floats2half2_rn(v.x, v.y);
        o[1] = __floats2half2_rn(v.z, v.w);
    }
}
__global__ void split_half(const float* __restrict__ s, __half* __restrict__ hi,
                           __half* __restrict__ lo, int n4) {
    int stride = gridDim.x * blockDim.x;
    for (int i = blockIdx.x * blockDim.x + threadIdx.x; i < n4; i += stride) {
        float4 v = ((const float4*)s)[i];
        __half h0 = __float2half(v.x), h1 = __float2half(v.y);
        __half h2 = __float2half(v.z), h3 = __float2half(v.w);
        ((__half2*)hi)[i * 2 + 0] = __halves2half2(h0, h1);
        ((__half2*)hi)[i * 2 + 1] = __halves2half2(h2, h3);
        ((__half2*)lo)[i * 2 + 0] = __halves2half2(
            __float2half(v.x - __half2float(h0)), __float2half(v.y - __half2float(h1)));
        ((__half2*)lo)[i * 2 + 1] = __halves2half2(
            __float2half(v.z - __half2float(h2)), __float2half(v.w - __half2float(h3)));
    }
}
__global__ void bias2(const float* a, const float* b, const float* c,
                      const float* d, float* o0, float* o1) {
    int i = blockIdx.x * 256 + threadIdx.x;
    if (i < kH) { o0[i] = a[i] + b[i]; o1[i] = c[i] + d[i]; }
}
__global__ void zero_flags() {
    int i = blockIdx.x * 256 + threadIdx.x;
    if (i < kT * 16) {
        ((int*)g_pf0)[i] = 0; ((int*)g_pf1)[i] = 0;
        ((int*)g_hf0)[i] = 0; ((int*)g_hf1)[i] = 0;
    }
}

// ---------------------------------------------------------------------------
// Big fp16-x2 GEMM for X0 (proven R14 kernel, unchanged)
// ---------------------------------------------------------------------------
#define GRS 144
#define GBUF (128 * GRS)
#define GEMM_SMEM (3 * GBUF)   // 55296

__global__ void __launch_bounds__(256) gemm_h(
    const __half* __restrict__ Ah, const __half* __restrict__ Whi,
    const __half* __restrict__ Wlo, const float* __restrict__ bias,
    float* __restrict__ C)
{
    extern __shared__ char sm[];
    char* pA  = sm;
    char* pWh = sm + GBUF;
    char* pWl = sm + 2 * GBUF;

    const int tid = threadIdx.x, lane = tid & 31, wid = tid >> 5;
    const int n0 = blockIdx.x * 128, m0 = blockIdx.y * 128;
    const int wm = (wid >> 1) * 32, wn = (wid & 1) * 64;

    const uint32_t aOff = smem_u32(pA) + (wm + (lane & 15)) * GRS + (lane >> 4) * 16;
    const int brow = wn + (lane & 7) + ((lane >> 4) & 1) * 8;
    const uint32_t bOffH = smem_u32(pWh) + brow * GRS + ((lane >> 3) & 1) * 16;
    const uint32_t bOffL = smem_u32(pWl) + brow * GRS + ((lane >> 3) & 1) * 16;

    float acc[2][8][4];
#pragma unroll
    for (int a = 0; a < 2; a++)
#pragma unroll
        for (int b = 0; b < 8; b++)
#pragma unroll
            for (int c = 0; c < 4; c++) acc[a][b][c] = 0.f;

    for (int k0 = 0; k0 < kH; k0 += 64) {
        __syncthreads();
#pragma unroll
        for (int i = 0; i < 4; i++) {
            int q = tid + i * 256;
            int row = q >> 3, c16 = q & 7;
            *(uint4*)(pA  + row * GRS + c16 * 16) =
                *((const uint4*)(Ah  + (size_t)(m0 + row) * kH + k0) + c16);
            *(uint4*)(pWh + row * GRS + c16 * 16) =
                *((const uint4*)(Whi + (size_t)(n0 + row) * kH + k0) + c16);
            *(uint4*)(pWl + row * GRS + c16 * 16) =
                *((const uint4*)(Wlo + (size_t)(n0 + row) * kH + k0) + c16);
        }
        __syncthreads();
#pragma unroll
        for (int kk = 0; kk < 4; kk++) {
            uint32_t ah0[4], ah1[4];
            LDSM4(ah0, aOff + kk * 32);
            LDSM4(ah1, aOff + 16 * GRS + kk * 32);
#pragma unroll
            for (int np = 0; np < 4; np++) {
                uint32_t bh[4], bl[4];
                LDSM4(bh, bOffH + np * 16 * GRS + kk * 32);
                LDSM4(bl, bOffL + np * 16 * GRS + kk * 32);
                HMMA(acc[0][np*2+0], ah0, bh+0); HMMA(acc[0][np*2+1], ah0, bh+2);
                HMMA(acc[1][np*2+0], ah1, bh+0); HMMA(acc[1][np*2+1], ah1, bh+2);
                HMMA(acc[0][np*2+0], ah0, bl+0); HMMA(acc[0][np*2+1], ah0, bl+2);
                HMMA(acc[1][np*2+0], ah1, bl+0); HMMA(acc[1][np*2+1], ah1, bl+2);
            }
        }
    }
    const int g = lane >> 2, tg2 = (lane & 3) * 2;
#pragma unroll
    for (int mf = 0; mf < 2; mf++)
#pragma unroll
        for (int nt = 0; nt < 8; nt++) {
            int m = m0 + wm + mf * 16 + g;
            int n = n0 + wn + nt * 8 + tg2;
            float b0 = bias[n], b1 = bias[n + 1];
            *(float2*)(C + (size_t)m * kH + n) =
                make_float2(acc[mf][nt][0] + b0, acc[mf][nt][1] + b1);
            *(float2*)(C + (size_t)(m + 8) * kH + n) =
                make_float2(acc[mf][nt][2] + b0, acc[mf][nt][3] + b1);
        }
}

// ---------------------------------------------------------------------------
// Warp-specialized fused recurrence, fp16 x2, 512 threads.
// 128 CTAs = 16 mt(64 cols) x 8 kc(128 k). Parallel flag polling (R16).
// Warps 0-7: layer0 (group A).  Warps 8-15: layer1 (group B).
// ---------------------------------------------------------------------------
#define RS2 272                       // 128 fp16 + 8 pad
#define SLW (64 * RS2)                // 17408: one W slice [64 rows][128 k]
#define OHA  (6 * SLW)
#define OHB0 (7 * SLW)
#define OHB1 (8 * SLW)
#define RNN_SMEM (9 * SLW)            // 156672

__device__ __forceinline__ void stage_h16(char* dst, const __half* __restrict__ src,
                                          int k0, int gtid)
{
#pragma unroll
    for (int i = 0; i < 4; i++) {
        int q = gtid + i * 256;                // 0..1023 (64 rows x 16 uint4)
        int row = q >> 4, c16 = q & 15;
        uint4 v = __ldcg((const uint4*)(src + (size_t)row * kH + k0) + c16);
        *(uint4*)(dst + row * RS2 + c16 * 16) = v;
    }
}

// fused dual staging: interleaved loads (2x MLP) for group B
__device__ __forceinline__ void stage_h16x2(char* d0, const __half* __restrict__ s0,
                                            char* d1, const __half* __restrict__ s1,
                                            int k0, int gtid)
{
#pragma unroll
    for (int i = 0; i < 4; i++) {
        int q = gtid + i * 256;
        int row = q >> 4, c16 = q & 15;
        size_t off = (size_t)row * kH + k0;
        uint4 v0 = __ldcg((const uint4*)(s0 + off) + c16);
        uint4 v1 = __ldcg((const uint4*)(s1 + off) + c16);
        *(uint4*)(d0 + row * RS2 + c16 * 16) = v0;
        *(uint4*)(d1 + row * RS2 + c16 * 16) = v1;
    }
}

__global__ void __launch_bounds__(512) rnn_ws(
    float* __restrict__ out_y, float* __restrict__ hfin0,
    float* __restrict__ hfin1)
{
    extern __shared__ char sm[];
    const int tid = threadIdx.x, lane = tid & 31, wid = tid >> 5;
    const int cta = blockIdx.x;
    const int mt = cta >> 3;                  // 0..15 (64 hidden cols)
    const int kc = cta & 7;                   // 0..7 (128-k chunk)
    const int h0c = mt * 64;
    const int k0 = kc * 128;
    const int kt0 = 2 * kc;                   // h-tiles covering our k range: kt0, kt0+1
    const int group = wid >> 3;               // 0 = layer0, 1 = layer1
    const int gw = wid & 7;
    const int gtid = tid & 255;

    // ---- cooperative staging of 6 step-invariant W slices [64 rows][128 k] ----
    {
        const __half* wsrc[6] = { g_s.Whi[1], g_s.Wlo[1], g_s.Whi[2],
                                  g_s.Wlo[2], g_s.Whi[3], g_s.Wlo[3] };
#pragma unroll
        for (int sl = 0; sl < 6; sl++) {
            char* dst = sm + sl * SLW;
            const __half* src = wsrc[sl];
#pragma unroll
            for (int i = 0; i < 2; i++) {
                int q = tid + i * 512;
                int row = q >> 4, c16 = q & 15;
                *(uint4*)(dst + row * RS2 + c16 * 16) =
                    *((const uint4*)(src + (size_t)(h0c + row) * kH + k0) + c16);
            }
        }
    }
    __syncthreads();    // LAST full-CTA sync; groups diverge permanently below

    const int bg = gw & 3, cg = gw >> 2;               // 16 b-rows x 32 cols
    const int bb = bg * 16;
    const uint32_t arow = (bb + (lane & 15)) * RS2 + (lane >> 4) * 16;
    const int brow = cg * 32 + (lane & 7) + ((lane >> 4) & 1) * 8;
    const uint32_t bsel = ((lane >> 3) & 1) * 16;

    const uint32_t bW0H = smem_u32(sm + 0 * SLW) + brow * RS2 + bsel;
    const uint32_t bW0L = smem_u32(sm + 1 * SLW) + brow * RS2 + bsel;
    const uint32_t bW1H = smem_u32(sm + 2 * SLW) + brow * RS2 + bsel;
    const uint32_t bW1L = smem_u32(sm + 3 * SLW) + brow * RS2 + bsel;
    const uint32_t bW2H = smem_u32(sm + 4 * SLW) + brow * RS2 + bsel;
    const uint32_t bW2L = smem_u32(sm + 5 * SLW) + brow * RS2 + bsel;

    const int g = lane >> 2, tg2 = (lane & 3) * 2;

    // reduce/publish ownership: 256 threads cover 64 rows x 8 cols (2 each)
    const int rb   = gtid >> 2;                        // batch row 0..63
    const int rcol = kc * 8 + (gtid & 3) * 2;          // col within 64-tile
    const int gcol = h0c + rcol;
    const int gidx = rb * kH + gcol;

    if (group == 0) {
        // ================= GROUP A: layer-0 serial chain =================
        char* pHA = sm + OHA;
        const uint32_t aH = smem_u32(pHA) + arow;

        for (int t = 0; t < kT; t++) {
            // parallel flag polling: threads 0,1 -> h deps; thread 2 -> slot guard
            if (t >= 1 && gtid < 2) spin_ge(&g_hf0[t - 1][kt0 + gtid], 8);
            if (t >= 4 && gtid == 2) spin_ge(&g_hf0[t - 4][mt], 8);
            BARA();
            stage_h16(pHA, t ? g_h0 + (size_t)(t - 1) * kBH : g_s.hin, k0, gtid);
            float2 xv = __ldcg((const float2*)(g_s.X + (size_t)t * kBH + gidx));
            BARA();

            float acc[4][4];
#pragma unroll
            for (int a = 0; a < 4; a++)
#pragma unroll
                for (int c = 0; c < 4; c++) acc[a][c] = 0.f;
#pragma unroll
            for (int kk = 0; kk < 8; kk++) {
                uint32_t ah[4];
                LDSM4(ah, aH + kk * 32);
#pragma unroll
                for (int np = 0; np < 2; np++) {
                    uint32_t wh[4], wl[4];
                    LDSM4(wh, bW0H + np * 16 * RS2 + kk * 32);
                    LDSM4(wl, bW0L + np * 16 * RS2 + kk * 32);
                    HMMA(acc[np*2+0], ah, wh+0); HMMA(acc[np*2+1], ah, wh+2);
                    HMMA(acc[np*2+0], ah, wl+0); HMMA(acc[np*2+1], ah, wl+2);
                }
            }

            float* pp = &g_p0[t & 3][mt][kc][0];
            const int b = bb + g;
#pragma unroll
            for (int nt = 0; nt < 4; nt++) {
                int col = cg * 32 + nt * 8 + tg2;
                *(float2*)(pp + b * 64 + col) = make_float2(acc[nt][0], acc[nt][1]);
                *(float2*)(pp + (b + 8) * 64 + col) = make_float2(acc[nt][2], acc[nt][3]);
            }
            BARA();
            if (gtid == 0) {
                __threadfence(); atomicAdd(&g_pf0[t][mt], 1);
                spin_ge(&g_pf0[t][mt], 8);
            }
            BARA();

            float2 s = xv;
            const float* base = &g_p0[t & 3][mt][0][0];
#pragma unroll
            for (int rr = 0; rr < 8; rr++) {
                float2 p = __ldcg((const float2*)(base + rr * 4096 + rb * 64 + rcol));
                s.x += p.x; s.y += p.y;
            }
            float hx = tanhf(s.x), hy = tanhf(s.y);
            *(__half2*)(g_h0 + (size_t)t * kBH + gidx) = __floats2half2_rn(hx, hy);
            if (t == kT - 1) *(float2*)(hfin0 + gidx) = make_float2(hx, hy);
            BARA();
            if (gtid == 0) { __threadfence(); atomicAdd(&g_hf0[t][mt], 1); }
        }
    } else {
        // ================= GROUP B: layer-1 trailing chain =================
        char* pB0 = sm + OHB0;
        char* pB1 = sm + OHB1;
        const uint32_t a0 = smem_u32(pB0) + arow;
        const uint32_t a1 = smem_u32(pB1) + arow;
        const float2 bv = *(const float2*)(g_s.bias[1] + gcol);

        for (int t = 0; t < kT; t++) {
            // parallel flag polling: 5 flags, 5 threads, one RT
            if (gtid < 2) spin_ge(&g_hf0[t][kt0 + gtid], 8);
            if (t >= 1 && (gtid == 2 || gtid == 3))
                spin_ge(&g_hf1[t - 1][kt0 + (gtid - 2)], 8);
            if (t >= 4 && gtid == 4) spin_ge(&g_hf1[t - 4][mt], 8);
            BARB();
            stage_h16x2(pB0, g_h0 + (size_t)t * kBH,
                        pB1, t ? g_h1 + (size_t)(t - 1) * kBH : g_s.hin + kBH,
                        k0, gtid);
            BARB();

            float acc[4][4];
#pragma unroll
            for (int a = 0; a < 4; a++)
#pragma unroll
                for (int c = 0; c < 4; c++) acc[a][c] = 0.f;
#pragma unroll
            for (int kk = 0; kk < 8; kk++) {
                uint32_t x0[4], x1[4];
                LDSM4(x0, a0 + kk * 32);
                LDSM4(x1, a1 + kk * 32);
#pragma unroll
                for (int np = 0; np < 2; np++) {
                    uint32_t w1h[4], w1l[4], w2h[4], w2l[4];
                    LDSM4(w1h, bW1H + np * 16 * RS2 + kk * 32);
                    LDSM4(w1l, bW1L + np * 16 * RS2 + kk * 32);
                    LDSM4(w2h, bW2H + np * 16 * RS2 + kk * 32);
                    LDSM4(w2l, bW2L + np * 16 * RS2 + kk * 32);
                    HMMA(acc[np*2+0], x0, w1h+0); HMMA(acc[np*2+1], x0, w1h+2);
                    HMMA(acc[np*2+0], x1, w2h+0); HMMA(acc[np*2+1], x1, w2h+2);
                    HMMA(acc[np*2+0], x0, w1l+0); HMMA(acc[np*2+1], x0, w1l+2);
                    HMMA(acc[np*2+0], x1, w2l+0); HMMA(acc[np*2+1], x1, w2l+2);
                }
            }

            float* pp = &g_p1[t & 3][mt][kc][0];
            const int b = bb + g;
#pragma unroll
            for (int nt = 0; nt < 4; nt++) {
                int col = cg * 32 + nt * 8 + tg2;
                *(float2*)(pp + b * 64 + col) = make_float2(acc[nt][0], acc[nt][1]);
                *(float2*)(pp + (b + 8) * 64 + col) = make_float2(acc[nt][2], acc[nt][3]);
            }
            BARB();
            if (gtid == 0) {
                __threadfence(); atomicAdd(&g_pf1[t][mt], 1);
                spin_ge(&g_pf1[t][mt], 8);
            }
            BARB();

            float2 s = bv;
            const float* base = &g_p1[t & 3][mt][0][0];
#pragma unroll
            for (int rr = 0; rr < 8; rr++) {
                float2 p = __ldcg((const float2*)(base + rr * 4096 + rb * 64 + rcol));
                s.x += p.x; s.y += p.y;
            }
            float hx = tanhf(s.x), hy = tanhf(s.y);
            *(float2*)(out_y + (size_t)t * kBH + gidx) = make_float2(hx, hy);
            *(__half2*)(g_h1 + (size_t)t * kBH + gidx) = __floats2half2_rn(hx, hy);
            if (t == kT - 1) *(float2*)(hfin1 + gidx) = make_float2(hx, hy);
            BARB();
            if (gtid == 0) { __threadfence(); atomicAdd(&g_hf1[t][mt], 1); }
        }
    }
}

// ---------------------------------------------------------------------------
// Launch
// ---------------------------------------------------------------------------
extern "C" void kernel_launch(void* const* d_in, const int* in_sizes, int n_in,
                              void* d_out, int out_size)
{
    const float* input = (const float*)d_in[0];
    const float* h_0   = (const float*)d_in[1];
    const float* W_ih0 = (const float*)d_in[2];
    const float* b_ih0 = (const float*)d_in[3];
    const float* W_hh0 = (const float*)d_in[4];
    const float* b_hh0 = (const float*)d_in[5];
    const float* W_ih1 = (const float*)d_in[6];
    const float* b_ih1 = (const float*)d_in[7];
    const float* W_hh1 = (const float*)d_in[8];
    const float* b_hh1 = (const float*)d_in[9];
    float* out = (float*)d_out;

    Scratch* s = nullptr;
    cudaGetSymbolAddress((void**)&s, g_s);

    cudaFuncSetAttribute(gemm_h, cudaFuncAttributeMaxDynamicSharedMemorySize, GEMM_SMEM);
    cudaFuncSetAttribute(rnn_ws, cudaFuncAttributeMaxDynamicSharedMemorySize, RNN_SMEM);

    zero_flags<<<32, 256>>>();
    cvt_half<<<2048, 256>>>(input, s->Ah, kTBH / 4);
    split_half<<<1024, 256>>>(W_ih0, s->Whi[0], s->Wlo[0], kH * kH / 4);
    split_half<<<1024, 256>>>(W_hh0, s->Whi[1], s->Wlo[1], kH * kH / 4);
    split_half<<<1024, 256>>>(W_ih1, s->Whi[2], s->Wlo[2], kH * kH / 4);
    split_half<<<1024, 256>>>(W_hh1, s->Whi[3], s->Wlo[3], kH * kH / 4);
    cvt_half<<<128, 256>>>(h_0, s->hin, 2 * kBH / 4);
    bias2<<<4, 256>>>(b_ih0, b_hh0, b_ih1, b_hh1, s->bias[0], s->bias[1]);

    dim3 ggrid(kH / 128, kTB / 128);
    gemm_h<<<ggrid, 256, GEMM_SMEM>>>(s->Ah, s->Whi[0], s->Wlo[0],
                                      s->bias[0], s->X);

    rnn_ws<<<128, 512, RNN_SMEM>>>(out, out + (size_t)kTBH,
                                   out + (size_t)kTBH + kBH);
}